// round 5
// baseline (speedup 1.0000x reference)
#include <cuda_runtime.h>

// ---------------------------------------------------------------------------
// ContActor: B=64, N=1024, D_IN=16, D=256, H=4, DH=64, L=3, DFF=1024, K=64
// Full fp32. Outputs (concatenated float32):
//   weights [64*1024], topk_idx (as float) [64*64], sel [64*64]
// Round 5: byte-identical resubmit (5 consecutive broker failures, still no
// hardware evidence; holding the two banked changes — gemm128 + baseline —
// for clean attribution on the first real bench).
// ---------------------------------------------------------------------------

#define BB   64
#define NNQ  1024
#define DIN  16
#define DD   256
#define HH   4
#define DHH  64
#define LLL  3
#define DFFN 1024
#define KKK  64
#define TOK  (BB * NNQ)   // 65536

// ------------------------- scratch (device globals) ------------------------
__device__ float g_h  [(size_t)TOK * DD];
__device__ float g_q  [(size_t)TOK * DD];
__device__ float g_k  [(size_t)TOK * DD];
__device__ float g_v  [(size_t)TOK * DD];
__device__ float g_o  [(size_t)TOK * DD];
__device__ float g_ffn[(size_t)TOK * DFFN];
__device__ float g_hmean[BB * DD];
__device__ float g_qv   [BB * DD];
__device__ float g_t1   [BB * DD];
__device__ float g_logits[BB * NNQ];
__device__ int   g_topk  [BB * KKK];

// --------------------- big GEMM: 128x128 tile, BK=16, 8x8 micro -------------
// C[M,N] = A[M,Kd] @ W[Kd,N] (+bias)(+relu). Requires M%128==0, N%128==0,
// Kd%16==0. Double-buffered smem, fully unrolled inner product.
#define BM 128
#define BN 128
#define BK 16

__global__ __launch_bounds__(256) void gemm128_kernel(
    const float* __restrict__ A, const float* __restrict__ W,
    const float* __restrict__ bias, float* __restrict__ C,
    int M, int N, int Kd, int do_relu)
{
    __shared__ float As[2][BK][BM + 4];   // [k][m], pitch 132 (16B-aligned)
    __shared__ float Bs[2][BK][BN];       // [k][n]

    int tid = threadIdx.x;
    int m0 = blockIdx.y * BM, n0 = blockIdx.x * BN;

    // A-load role: row ar (0..127), col half ac (0 or 8) -> 8 floats along k
    int ar = tid >> 1;
    int ac = (tid & 1) << 3;
    // B-load role: row br (0..15), col bc (0..120 step 8) -> 8 floats along n
    int br = tid >> 4;
    int bc = (tid & 15) << 3;

    // compute role: 8x8 micro-tile at (ty*8, tx*8)
    int tx = tid & 15, ty = tid >> 4;

    const int nt = Kd / BK;

    float acc[8][8] = {};
    float4 pa0, pa1, pb0, pb1;

    // --- preload tile 0 into buffer 0 ---
    {
        const float* ap = A + (size_t)(m0 + ar) * Kd + ac;
        pa0 = *(const float4*)(ap);
        pa1 = *(const float4*)(ap + 4);
        const float* bp = W + (size_t)br * N + n0 + bc;
        pb0 = *(const float4*)(bp);
        pb1 = *(const float4*)(bp + 4);

        As[0][ac + 0][ar] = pa0.x;  As[0][ac + 1][ar] = pa0.y;
        As[0][ac + 2][ar] = pa0.z;  As[0][ac + 3][ar] = pa0.w;
        As[0][ac + 4][ar] = pa1.x;  As[0][ac + 5][ar] = pa1.y;
        As[0][ac + 6][ar] = pa1.z;  As[0][ac + 7][ar] = pa1.w;
        *(float4*)&Bs[0][br][bc]     = pb0;
        *(float4*)&Bs[0][br][bc + 4] = pb1;
    }
    __syncthreads();

    for (int kt = 0; kt < nt; kt++) {
        int cur = kt & 1, nxt = cur ^ 1;

        // issue next tile's global loads early (overlap with compute)
        if (kt + 1 < nt) {
            int k0 = (kt + 1) * BK;
            const float* ap = A + (size_t)(m0 + ar) * Kd + k0 + ac;
            pa0 = *(const float4*)(ap);
            pa1 = *(const float4*)(ap + 4);
            const float* bp = W + (size_t)(k0 + br) * N + n0 + bc;
            pb0 = *(const float4*)(bp);
            pb1 = *(const float4*)(bp + 4);
        }

        #pragma unroll
        for (int k = 0; k < BK; k++) {
            float a[8], b[8];
            *(float4*)&a[0] = *(float4*)&As[cur][k][ty * 8];
            *(float4*)&a[4] = *(float4*)&As[cur][k][ty * 8 + 4];
            *(float4*)&b[0] = *(float4*)&Bs[cur][k][tx * 8];
            *(float4*)&b[4] = *(float4*)&Bs[cur][k][tx * 8 + 4];
            #pragma unroll
            for (int i = 0; i < 8; i++)
                #pragma unroll
                for (int j = 0; j < 8; j++)
                    acc[i][j] += a[i] * b[j];
        }

        if (kt + 1 < nt) {
            As[nxt][ac + 0][ar] = pa0.x;  As[nxt][ac + 1][ar] = pa0.y;
            As[nxt][ac + 2][ar] = pa0.z;  As[nxt][ac + 3][ar] = pa0.w;
            As[nxt][ac + 4][ar] = pa1.x;  As[nxt][ac + 5][ar] = pa1.y;
            As[nxt][ac + 6][ar] = pa1.z;  As[nxt][ac + 7][ar] = pa1.w;
            *(float4*)&Bs[nxt][br][bc]     = pb0;
            *(float4*)&Bs[nxt][br][bc + 4] = pb1;
        }
        __syncthreads();
    }

    // epilogue
    #pragma unroll
    for (int i = 0; i < 8; i++) {
        float* crow = C + (size_t)(m0 + ty * 8 + i) * N + n0 + tx * 8;
        #pragma unroll
        for (int j4 = 0; j4 < 8; j4 += 4) {
            float4 o;
            float* po = (float*)&o;
            #pragma unroll
            for (int j = 0; j < 4; j++) {
                float v = acc[i][j4 + j];
                if (bias) v += bias[n0 + tx * 8 + j4 + j];
                if (do_relu) v = fmaxf(v, 0.f);
                po[j] = v;
            }
            *(float4*)(crow + j4) = o;
        }
    }
}

// --------------------- small GEMM: 64x64 tile, BK=32, 4x4 micro --------------
__global__ __launch_bounds__(256) void gemm_kernel(
    const float* __restrict__ A, const float* __restrict__ W,
    const float* __restrict__ bias, float* __restrict__ C,
    int M, int N, int Kd, int do_relu)
{
    __shared__ float As[64][36];
    __shared__ float Bs[32][64];
    int tid = threadIdx.x;
    int tx = tid & 15, ty = tid >> 4;
    int m0 = blockIdx.y << 6, n0 = blockIdx.x << 6;

    float acc[4][4] = {};

    for (int k0 = 0; k0 < Kd; k0 += 32) {
        {
            int r  = tid >> 3;
            int c4 = (tid & 7) << 2;
            #pragma unroll
            for (int rr = 0; rr < 64; rr += 32) {
                float4 val;
                if (k0 + c4 < Kd)
                    val = *(const float4*)(A + (size_t)(m0 + r + rr) * Kd + k0 + c4);
                else
                    val = make_float4(0.f, 0.f, 0.f, 0.f);
                *(float4*)&As[r + rr][c4] = val;
            }
        }
        {
            int r  = tid >> 4;
            int c4 = (tid & 15) << 2;
            #pragma unroll
            for (int rr = 0; rr < 32; rr += 16) {
                float4 val;
                if (k0 + r + rr < Kd)
                    val = *(const float4*)(W + (size_t)(k0 + r + rr) * N + n0 + c4);
                else
                    val = make_float4(0.f, 0.f, 0.f, 0.f);
                *(float4*)&Bs[r + rr][c4] = val;
            }
        }
        __syncthreads();
        #pragma unroll
        for (int k = 0; k < 32; k++) {
            float4 bv = *(float4*)&Bs[k][tx << 2];
            float b[4] = {bv.x, bv.y, bv.z, bv.w};
            float a[4];
            #pragma unroll
            for (int i = 0; i < 4; i++) a[i] = As[(ty << 2) + i][k];
            #pragma unroll
            for (int i = 0; i < 4; i++)
                #pragma unroll
                for (int j = 0; j < 4; j++)
                    acc[i][j] += a[i] * b[j];
        }
        __syncthreads();
    }

    #pragma unroll
    for (int i = 0; i < 4; i++) {
        float4 out;
        float* po = (float*)&out;
        #pragma unroll
        for (int j = 0; j < 4; j++) {
            float v = acc[i][j];
            if (bias) v += bias[n0 + (tx << 2) + j];
            if (do_relu) v = fmaxf(v, 0.f);
            po[j] = v;
        }
        *(float4*)(C + (size_t)(m0 + (ty << 2) + i) * N + n0 + (tx << 2)) = out;
    }
}

// ----------------------------- attention -------------------------------------
#define ATTN_SMEM_FLOATS (32 * 1024 + 32 * 64 + 64 * 65)
__global__ __launch_bounds__(256) void attn_kernel(
    const float* __restrict__ Q, const float* __restrict__ Kf,
    const float* __restrict__ V, float* __restrict__ O)
{
    extern __shared__ float sm[];
    float* sS = sm;                      // [32][1024]
    float* sQ = sm + 32 * 1024;          // [32][64]
    float* sK = sQ + 32 * 64;            // [64][65]

    int tid = threadIdx.x;
    int bh  = blockIdx.y;
    int b   = bh >> 2, h = bh & 3;
    int n0  = blockIdx.x << 5;
    size_t base = ((size_t)b * NNQ) * DD + h * DHH;

    for (int idx = tid; idx < 32 * 64; idx += 256) {
        int r = idx >> 6, d = idx & 63;
        sQ[idx] = Q[base + (size_t)(n0 + r) * DD + d];
    }
    int wid = tid >> 5, lane = tid & 31;

    for (int kt = 0; kt < 16; kt++) {
        __syncthreads();
        for (int idx = tid; idx < 64 * 64; idx += 256) {
            int r = idx >> 6, d = idx & 63;
            sK[r * 65 + d] = Kf[base + (size_t)(kt * 64 + r) * DD + d];
        }
        __syncthreads();
        float acc[4][2] = {};
        #pragma unroll 8
        for (int d = 0; d < 64; d++) {
            float b0 = sK[lane * 65 + d];
            float b1 = sK[(lane + 32) * 65 + d];
            #pragma unroll
            for (int i = 0; i < 4; i++) {
                float a = sQ[((wid << 2) + i) * 64 + d];
                acc[i][0] += a * b0;
                acc[i][1] += a * b1;
            }
        }
        #pragma unroll
        for (int i = 0; i < 4; i++) {
            sS[((wid << 2) + i) * 1024 + (kt << 6) + lane]      = acc[i][0] * 0.125f;
            sS[((wid << 2) + i) * 1024 + (kt << 6) + lane + 32] = acc[i][1] * 0.125f;
        }
    }
    __syncthreads();

    #pragma unroll
    for (int rr = 0; rr < 4; rr++) {
        float* row = sS + ((wid << 2) + rr) * 1024;
        float mx = -1e30f;
        for (int c = lane; c < 1024; c += 32) mx = fmaxf(mx, row[c]);
        #pragma unroll
        for (int o = 16; o > 0; o >>= 1) mx = fmaxf(mx, __shfl_xor_sync(~0u, mx, o));
        float s = 0.f;
        for (int c = lane; c < 1024; c += 32) {
            float e = expf(row[c] - mx); row[c] = e; s += e;
        }
        #pragma unroll
        for (int o = 16; o > 0; o >>= 1) s += __shfl_xor_sync(~0u, s, o);
        float inv = 1.f / s;
        for (int c = lane; c < 1024; c += 32) row[c] *= inv;
    }

    float oacc[4][2] = {};
    for (int vt = 0; vt < 16; vt++) {
        __syncthreads();
        for (int idx = tid; idx < 64 * 64; idx += 256) {
            int r = idx >> 6, d = idx & 63;
            sK[r * 65 + d] = V[base + (size_t)(vt * 64 + r) * DD + d];
        }
        __syncthreads();
        #pragma unroll 8
        for (int jj = 0; jj < 64; jj++) {
            float v0 = sK[jj * 65 + lane];
            float v1 = sK[jj * 65 + lane + 32];
            #pragma unroll
            for (int i = 0; i < 4; i++) {
                float p = sS[((wid << 2) + i) * 1024 + (vt << 6) + jj];
                oacc[i][0] += p * v0;
                oacc[i][1] += p * v1;
            }
        }
    }
    #pragma unroll
    for (int i = 0; i < 4; i++) {
        O[base + (size_t)(n0 + (wid << 2) + i) * DD + lane]      = oacc[i][0];
        O[base + (size_t)(n0 + (wid << 2) + i) * DD + lane + 32] = oacc[i][1];
    }
}

// ------------------------- residual + layernorm -----------------------------
__global__ __launch_bounds__(256) void lnres_kernel(
    float* __restrict__ Hb, const float* __restrict__ R,
    const float* __restrict__ gam, const float* __restrict__ bet)
{
    int token = (blockIdx.x << 3) + (threadIdx.x >> 5);
    int lane  = threadIdx.x & 31;
    float* hr = Hb + (size_t)token * DD;
    const float* rr = R + (size_t)token * DD;

    float vals[8];
    float s = 0.f;
    #pragma unroll
    for (int t = 0; t < 8; t++) {
        float v = hr[lane + (t << 5)] + rr[lane + (t << 5)];
        vals[t] = v; s += v;
    }
    #pragma unroll
    for (int o = 16; o > 0; o >>= 1) s += __shfl_xor_sync(~0u, s, o);
    float mean = s * (1.f / 256.f);
    float vs = 0.f;
    #pragma unroll
    for (int t = 0; t < 8; t++) { float d = vals[t] - mean; vs += d * d; }
    #pragma unroll
    for (int o = 16; o > 0; o >>= 1) vs += __shfl_xor_sync(~0u, vs, o);
    float inv = 1.f / sqrtf(vs * (1.f / 256.f) + 1e-5f);
    #pragma unroll
    for (int t = 0; t < 8; t++) {
        int d = lane + (t << 5);
        hr[d] = (vals[t] - mean) * inv * gam[d] + bet[d];
    }
}

// ------------------------------- mean over N --------------------------------
__global__ void mean_kernel(const float* __restrict__ H, float* __restrict__ Hm)
{
    int b = blockIdx.x, d = threadIdx.x;
    const float* p = H + (size_t)b * NNQ * DD + d;
    float s = 0.f;
    for (int n = 0; n < NNQ; n++) s += p[(size_t)n * DD];
    Hm[b * DD + d] = s * (1.f / 1024.f);
}

// ---------------- scores + gumbel-softmax weights (per batch b) -------------
__global__ __launch_bounds__(256) void score_kernel(
    const float* __restrict__ QV, const float* __restrict__ KV,
    const float* __restrict__ gum, float* __restrict__ outw)
{
    __shared__ float sqv[256];
    __shared__ float ss[1024];
    __shared__ float red[8];
    int b = blockIdx.x, tid = threadIdx.x;
    int wid = tid >> 5, lane = tid & 31;

    sqv[tid] = QV[b * 256 + tid];
    __syncthreads();

    for (int n = wid; n < 1024; n += 8) {
        const float* kr = KV + ((size_t)b * NNQ + n) * DD;
        float s = 0.f;
        #pragma unroll
        for (int t = 0; t < 8; t++) s += sqv[lane + (t << 5)] * kr[lane + (t << 5)];
        #pragma unroll
        for (int o = 16; o > 0; o >>= 1) s += __shfl_xor_sync(~0u, s, o);
        if (lane == 0) ss[n] = (s * 0.0625f + gum[b * NNQ + n]) * 2.0f;
    }
    __syncthreads();

    float mx = -1e30f;
    for (int c = tid; c < 1024; c += 256) mx = fmaxf(mx, ss[c]);
    #pragma unroll
    for (int o = 16; o > 0; o >>= 1) mx = fmaxf(mx, __shfl_xor_sync(~0u, mx, o));
    if (lane == 0) red[wid] = mx;
    __syncthreads();
    float bm = -1e30f;
    #pragma unroll
    for (int i = 0; i < 8; i++) bm = fmaxf(bm, red[i]);
    __syncthreads();

    float sum = 0.f;
    for (int c = tid; c < 1024; c += 256) {
        float e = expf(ss[c] - bm); ss[c] = e; sum += e;
    }
    #pragma unroll
    for (int o = 16; o > 0; o >>= 1) sum += __shfl_xor_sync(~0u, sum, o);
    if (lane == 0) red[wid] = sum;
    __syncthreads();
    float tot = 0.f;
    #pragma unroll
    for (int i = 0; i < 8; i++) tot += red[i];
    float inv = 1.f / tot;
    for (int c = tid; c < 1024; c += 256)
        outw[b * NNQ + c] = ss[c] * inv;
}

// ------------------------- top-k via bitonic sort ---------------------------
__global__ __launch_bounds__(512) void topk_kernel(
    const float* __restrict__ Wts, int* __restrict__ idx_out,
    float* __restrict__ idxf_out)
{
    __shared__ float sv[1024];
    __shared__ int   si[1024];
    int b = blockIdx.x, tid = threadIdx.x;
    for (int i = tid; i < 1024; i += 512) { sv[i] = Wts[b * 1024 + i]; si[i] = i; }
    __syncthreads();
    for (int k = 2; k <= 1024; k <<= 1) {
        for (int j = k >> 1; j > 0; j >>= 1) {
            for (int i = tid; i < 1024; i += 512) {
                int ix = i ^ j;
                if (ix > i) {
                    bool up = ((i & k) == 0);
                    float v1 = sv[i], v2 = sv[ix];
                    int   i1 = si[i], i2 = si[ix];
                    bool before = (v1 > v2) || (v1 == v2 && i1 < i2);
                    if (up ? !before : before) {
                        sv[i] = v2; sv[ix] = v1;
                        si[i] = i2; si[ix] = i1;
                    }
                }
            }
            __syncthreads();
        }
    }
    if (tid < KKK) {
        idx_out[b * KKK + tid]  = si[tid];
        idxf_out[b * KKK + tid] = (float)si[tid];
    }
}

// --------------------- alloc softmax + gather + renorm ----------------------
__global__ __launch_bounds__(256) void sel_kernel(
    const float* __restrict__ logits, const int* __restrict__ tk,
    float* __restrict__ sel_out)
{
    __shared__ float sl[1024];
    __shared__ float red[8];
    __shared__ float ssum;
    int b = blockIdx.x, tid = threadIdx.x;
    int wid = tid >> 5, lane = tid & 31;

    for (int c = tid; c < 1024; c += 256) sl[c] = logits[b * 1024 + c];
    __syncthreads();

    float mx = -1e30f;
    for (int c = tid; c < 1024; c += 256) mx = fmaxf(mx, sl[c]);
    #pragma unroll
    for (int o = 16; o > 0; o >>= 1) mx = fmaxf(mx, __shfl_xor_sync(~0u, mx, o));
    if (lane == 0) red[wid] = mx;
    __syncthreads();
    float bm = -1e30f;
    #pragma unroll
    for (int i = 0; i < 8; i++) bm = fmaxf(bm, red[i]);
    __syncthreads();

    float sum = 0.f;
    for (int c = tid; c < 1024; c += 256) {
        float e = expf(sl[c] - bm); sl[c] = e; sum += e;
    }
    #pragma unroll
    for (int o = 16; o > 0; o >>= 1) sum += __shfl_xor_sync(~0u, sum, o);
    if (lane == 0) red[wid] = sum;
    __syncthreads();
    float tot = 0.f;
    #pragma unroll
    for (int i = 0; i < 8; i++) tot += red[i];
    float inv = 1.f / tot;
    __syncthreads();
    for (int c = tid; c < 1024; c += 256) sl[c] *= inv;
    __syncthreads();

    if (tid == 0) {
        float s = 0.f;
        for (int kk = 0; kk < KKK; kk++) s += sl[tk[b * KKK + kk]];
        ssum = s;
    }
    __syncthreads();
    if (tid < KKK) {
        float v = sl[tk[b * KKK + tid]];
        sel_out[b * KKK + tid] = v / (ssum + 1e-12f);
    }
}

// ------------------------------- launcher -----------------------------------
static inline void launch_gemm(const float* A, const float* W, const float* bias,
                               float* C, int M, int N, int Kd, int relu)
{
    if ((M % 128 == 0) && (N % 128 == 0) && (Kd % 16 == 0)) {
        dim3 grid(N / 128, M / 128);
        gemm128_kernel<<<grid, 256>>>(A, W, bias, C, M, N, Kd, relu);
    } else {
        dim3 grid(N / 64, M / 64);
        gemm_kernel<<<grid, 256>>>(A, W, bias, C, M, N, Kd, relu);
    }
}

extern "C" void kernel_launch(void* const* d_in, const int* in_sizes, int n_in,
                              void* d_out, int out_size)
{
    const float* x      = (const float*)d_in[0];
    const float* gumbel = (const float*)d_in[1];
    const float* emb_W  = (const float*)d_in[2];
    const float* emb_b  = (const float*)d_in[3];
    const float* Wq     = (const float*)d_in[4];
    const float* Wk     = (const float*)d_in[5];
    const float* Wv     = (const float*)d_in[6];
    const float* Wo     = (const float*)d_in[7];
    const float* ln1_g  = (const float*)d_in[8];
    const float* ln1_b  = (const float*)d_in[9];
    const float* ln2_g  = (const float*)d_in[10];
    const float* ln2_b  = (const float*)d_in[11];
    const float* ffn_W1 = (const float*)d_in[12];
    const float* ffn_b1 = (const float*)d_in[13];
    const float* ffn_W2 = (const float*)d_in[14];
    const float* ffn_b2 = (const float*)d_in[15];
    const float* sha_Wq = (const float*)d_in[16];
    const float* sha_Wk = (const float*)d_in[17];
    const float* aW1    = (const float*)d_in[18];
    const float* ab1    = (const float*)d_in[19];
    const float* aW2    = (const float*)d_in[20];
    const float* ab2    = (const float*)d_in[21];

    float* out     = (float*)d_out;
    float* out_w   = out;                  // [64*1024]
    float* out_idx = out + BB * NNQ;       // [64*64] indices as float
    float* out_sel = out_idx + BB * KKK;   // [64*64]

    float *ph, *pq, *pk, *pv, *po, *pffn, *phm, *pqv, *pt1, *plog;
    int* ptk;
    cudaGetSymbolAddress((void**)&ph,   g_h);
    cudaGetSymbolAddress((void**)&pq,   g_q);
    cudaGetSymbolAddress((void**)&pk,   g_k);
    cudaGetSymbolAddress((void**)&pv,   g_v);
    cudaGetSymbolAddress((void**)&po,   g_o);
    cudaGetSymbolAddress((void**)&pffn, g_ffn);
    cudaGetSymbolAddress((void**)&phm,  g_hmean);
    cudaGetSymbolAddress((void**)&pqv,  g_qv);
    cudaGetSymbolAddress((void**)&pt1,  g_t1);
    cudaGetSymbolAddress((void**)&plog, g_logits);
    cudaGetSymbolAddress((void**)&ptk,  g_topk);

    size_t attn_smem = (size_t)ATTN_SMEM_FLOATS * sizeof(float);
    cudaFuncSetAttribute(attn_kernel, cudaFuncAttributeMaxDynamicSharedMemorySize,
                         (int)attn_smem);

    // embed: h = x @ emb_W + emb_b
    launch_gemm(x, emb_W, emb_b, ph, TOK, DD, DIN, 0);

    for (int i = 0; i < LLL; i++) {
        const float* wq = Wq + (size_t)i * DD * DD;
        const float* wk = Wk + (size_t)i * DD * DD;
        const float* wv = Wv + (size_t)i * DD * DD;
        const float* wo = Wo + (size_t)i * DD * DD;

        launch_gemm(ph, wq, nullptr, pq, TOK, DD, DD, 0);
        launch_gemm(ph, wk, nullptr, pk, TOK, DD, DD, 0);
        launch_gemm(ph, wv, nullptr, pv, TOK, DD, DD, 0);

        attn_kernel<<<dim3(NNQ / 32, BB * HH), 256, attn_smem>>>(pq, pk, pv, po);

        launch_gemm(po, wo, nullptr, pq, TOK, DD, DD, 0);
        lnres_kernel<<<TOK / 8, 256>>>(ph, pq, ln1_g + i * DD, ln1_b + i * DD);

        launch_gemm(ph, ffn_W1 + (size_t)i * DD * DFFN, ffn_b1 + i * DFFN,
                    pffn, TOK, DFFN, DD, 1);
        launch_gemm(pffn, ffn_W2 + (size_t)i * DFFN * DD, ffn_b2 + i * DD,
                    pq, TOK, DD, DFFN, 0);
        lnres_kernel<<<TOK / 8, 256>>>(ph, pq, ln2_g + i * DD, ln2_b + i * DD);
    }

    // head
    mean_kernel<<<BB, DD>>>(ph, phm);
    launch_gemm(phm, sha_Wq, nullptr, pqv, BB, DD, DD, 0);   // qv  [64,256]
    launch_gemm(ph, sha_Wk, nullptr, pk, TOK, DD, DD, 0);    // kv  [65536,256]

    score_kernel<<<BB, 256>>>(pqv, pk, gumbel, out_w);
    topk_kernel<<<BB, 512>>>(out_w, ptk, out_idx);

    launch_gemm(phm, aW1, ab1, pt1, BB, DD, DD, 1);          // relu(hmean@W1+b1)
    launch_gemm(pt1, aW2, ab2, plog, BB, NNQ, DD, 0);        // logits [64,1024]
    sel_kernel<<<BB, 256>>>(plog, ptk, out_sel);
}

// round 7
// speedup vs baseline: 1.9964x; 1.9964x over previous
#include <cuda_runtime.h>

// ---------------------------------------------------------------------------
// ContActor: B=64, N=1024, D_IN=16, D=256, H=4, DH=64, L=3, DFF=1024, K=64
// Full fp32. Outputs (concatenated float32):
//   weights [64*1024], topk_idx (as float) [64*64], sel [64*64]
// Round 7: byte-identical resubmit of round 6 (infra failure; fattn rewrite
// re-audited: swizzle bijective, 2-way store conflicts, reduction scopes OK).
// ---------------------------------------------------------------------------

#define BB   64
#define NNQ  1024
#define DIN  16
#define DD   256
#define HH   4
#define DHH  64
#define LLL  3
#define DFFN 1024
#define KKK  64
#define TOK  (BB * NNQ)   // 65536

// ------------------------- scratch (device globals) ------------------------
__device__ float g_h  [(size_t)TOK * DD];
__device__ float g_q  [(size_t)TOK * DD];
__device__ float g_k  [(size_t)TOK * DD];
__device__ float g_v  [(size_t)TOK * DD];
__device__ float g_o  [(size_t)TOK * DD];
__device__ float g_ffn[(size_t)TOK * DFFN];
__device__ float g_hmean[BB * DD];
__device__ float g_qv   [BB * DD];
__device__ float g_t1   [BB * DD];
__device__ float g_logits[BB * NNQ];
__device__ int   g_topk  [BB * KKK];

// --------------------- big GEMM: 128x128 tile, BK=16, 8x8 micro -------------
#define BM 128
#define BN 128
#define BK 16

__global__ __launch_bounds__(256) void gemm128_kernel(
    const float* __restrict__ A, const float* __restrict__ W,
    const float* __restrict__ bias, float* __restrict__ C,
    int M, int N, int Kd, int do_relu)
{
    __shared__ float As[2][BK][BM + 4];
    __shared__ float Bs[2][BK][BN];

    int tid = threadIdx.x;
    int m0 = blockIdx.y * BM, n0 = blockIdx.x * BN;

    int ar = tid >> 1;
    int ac = (tid & 1) << 3;
    int br = tid >> 4;
    int bc = (tid & 15) << 3;
    int tx = tid & 15, ty = tid >> 4;

    const int nt = Kd / BK;

    float acc[8][8] = {};
    float4 pa0, pa1, pb0, pb1;

    {
        const float* ap = A + (size_t)(m0 + ar) * Kd + ac;
        pa0 = *(const float4*)(ap);
        pa1 = *(const float4*)(ap + 4);
        const float* bp = W + (size_t)br * N + n0 + bc;
        pb0 = *(const float4*)(bp);
        pb1 = *(const float4*)(bp + 4);

        As[0][ac + 0][ar] = pa0.x;  As[0][ac + 1][ar] = pa0.y;
        As[0][ac + 2][ar] = pa0.z;  As[0][ac + 3][ar] = pa0.w;
        As[0][ac + 4][ar] = pa1.x;  As[0][ac + 5][ar] = pa1.y;
        As[0][ac + 6][ar] = pa1.z;  As[0][ac + 7][ar] = pa1.w;
        *(float4*)&Bs[0][br][bc]     = pb0;
        *(float4*)&Bs[0][br][bc + 4] = pb1;
    }
    __syncthreads();

    for (int kt = 0; kt < nt; kt++) {
        int cur = kt & 1, nxt = cur ^ 1;

        if (kt + 1 < nt) {
            int k0 = (kt + 1) * BK;
            const float* ap = A + (size_t)(m0 + ar) * Kd + k0 + ac;
            pa0 = *(const float4*)(ap);
            pa1 = *(const float4*)(ap + 4);
            const float* bp = W + (size_t)(k0 + br) * N + n0 + bc;
            pb0 = *(const float4*)(bp);
            pb1 = *(const float4*)(bp + 4);
        }

        #pragma unroll
        for (int k = 0; k < BK; k++) {
            float a[8], b[8];
            *(float4*)&a[0] = *(float4*)&As[cur][k][ty * 8];
            *(float4*)&a[4] = *(float4*)&As[cur][k][ty * 8 + 4];
            *(float4*)&b[0] = *(float4*)&Bs[cur][k][tx * 8];
            *(float4*)&b[4] = *(float4*)&Bs[cur][k][tx * 8 + 4];
            #pragma unroll
            for (int i = 0; i < 8; i++)
                #pragma unroll
                for (int j = 0; j < 8; j++)
                    acc[i][j] += a[i] * b[j];
        }

        if (kt + 1 < nt) {
            As[nxt][ac + 0][ar] = pa0.x;  As[nxt][ac + 1][ar] = pa0.y;
            As[nxt][ac + 2][ar] = pa0.z;  As[nxt][ac + 3][ar] = pa0.w;
            As[nxt][ac + 4][ar] = pa1.x;  As[nxt][ac + 5][ar] = pa1.y;
            As[nxt][ac + 6][ar] = pa1.z;  As[nxt][ac + 7][ar] = pa1.w;
            *(float4*)&Bs[nxt][br][bc]     = pb0;
            *(float4*)&Bs[nxt][br][bc + 4] = pb1;
        }
        __syncthreads();
    }

    #pragma unroll
    for (int i = 0; i < 8; i++) {
        float* crow = C + (size_t)(m0 + ty * 8 + i) * N + n0 + tx * 8;
        #pragma unroll
        for (int j4 = 0; j4 < 8; j4 += 4) {
            float4 o;
            float* po = (float*)&o;
            #pragma unroll
            for (int j = 0; j < 4; j++) {
                float v = acc[i][j4 + j];
                if (bias) v += bias[n0 + tx * 8 + j4 + j];
                if (do_relu) v = fmaxf(v, 0.f);
                po[j] = v;
            }
            *(float4*)(crow + j4) = o;
        }
    }
}

// --------------------- small GEMM: 64x64 tile, BK=32, 4x4 micro --------------
__global__ __launch_bounds__(256) void gemm_kernel(
    const float* __restrict__ A, const float* __restrict__ W,
    const float* __restrict__ bias, float* __restrict__ C,
    int M, int N, int Kd, int do_relu)
{
    __shared__ float As[64][36];
    __shared__ float Bs[32][64];
    int tid = threadIdx.x;
    int tx = tid & 15, ty = tid >> 4;
    int m0 = blockIdx.y << 6, n0 = blockIdx.x << 6;

    float acc[4][4] = {};

    for (int k0 = 0; k0 < Kd; k0 += 32) {
        {
            int r  = tid >> 3;
            int c4 = (tid & 7) << 2;
            #pragma unroll
            for (int rr = 0; rr < 64; rr += 32) {
                float4 val;
                if (k0 + c4 < Kd)
                    val = *(const float4*)(A + (size_t)(m0 + r + rr) * Kd + k0 + c4);
                else
                    val = make_float4(0.f, 0.f, 0.f, 0.f);
                *(float4*)&As[r + rr][c4] = val;
            }
        }
        {
            int r  = tid >> 4;
            int c4 = (tid & 15) << 2;
            #pragma unroll
            for (int rr = 0; rr < 32; rr += 16) {
                float4 val;
                if (k0 + r + rr < Kd)
                    val = *(const float4*)(W + (size_t)(k0 + r + rr) * N + n0 + c4);
                else
                    val = make_float4(0.f, 0.f, 0.f, 0.f);
                *(float4*)&Bs[r + rr][c4] = val;
            }
        }
        __syncthreads();
        #pragma unroll
        for (int k = 0; k < 32; k++) {
            float4 bv = *(float4*)&Bs[k][tx << 2];
            float b[4] = {bv.x, bv.y, bv.z, bv.w};
            float a[4];
            #pragma unroll
            for (int i = 0; i < 4; i++) a[i] = As[(ty << 2) + i][k];
            #pragma unroll
            for (int i = 0; i < 4; i++)
                #pragma unroll
                for (int j = 0; j < 4; j++)
                    acc[i][j] += a[i] * b[j];
        }
        __syncthreads();
    }

    #pragma unroll
    for (int i = 0; i < 4; i++) {
        float4 out;
        float* po = (float*)&out;
        #pragma unroll
        for (int j = 0; j < 4; j++) {
            float v = acc[i][j];
            if (bias) v += bias[n0 + (tx << 2) + j];
            if (do_relu) v = fmaxf(v, 0.f);
            po[j] = v;
        }
        *(float4*)(C + (size_t)(m0 + (ty << 2) + i) * N + n0 + (tx << 2)) = out;
    }
}

// ---------------------- flash attention (64q x 64k tiles) -------------------
// One CTA per (b,h, 64-query tile). Online softmax; S never materialized
// beyond one 64x64 tile. All matmuls register-tiled 4x4 with float4 LDS.
// sQ/sK/sS are stored "dim-major transposed" with a 16B-chunk XOR swizzle to
// keep the transpose scatter-stores at <=2-way conflict while reads stay
// conflict-free float4.
#define APITCH 68   // floats per row (64 + 4 pad), 272B (16B aligned)
#define FATTN_SMEM_FLOATS (4 * 64 * APITCH)

__global__ __launch_bounds__(256, 2) void fattn_kernel(
    const float* __restrict__ Q, const float* __restrict__ Kf,
    const float* __restrict__ V, float* __restrict__ O)
{
    extern __shared__ float sm[];
    float* sQ = sm;                      // [d][q] swizzled
    float* sK = sQ + 64 * APITCH;        // [d][k] swizzled
    float* sV = sK + 64 * APITCH;        // [j][d] natural
    float* sS = sV + 64 * APITCH;        // [j][q] swizzled

    int tid = threadIdx.x;
    int tx = tid & 15, ty = tid >> 4;
    int bh = blockIdx.y;
    int b  = bh >> 2, h = bh & 3;
    int q0 = blockIdx.x << 6;
    size_t base = ((size_t)b * NNQ) * DD + h * DHH;

    // ---- load Q tile transposed (rows q0..q0+63, dims 0..63) ----
    #pragma unroll
    for (int it = 0; it < 4; it++) {
        int idx = tid + it * 256;
        int r = idx >> 4;            // 0..63
        int d4 = (idx & 15) << 2;    // 0..60
        float4 qv = *(const float4*)(Q + base + (size_t)(q0 + r) * DD + d4);
        int sw = ((d4 >> 2) & 7) << 2;            // same for d4..d4+3
        int cbase = (((r >> 2) << 2) ^ sw) + (r & 3);
        sQ[(d4 + 0) * APITCH + cbase] = qv.x;
        sQ[(d4 + 1) * APITCH + cbase] = qv.y;
        sQ[(d4 + 2) * APITCH + cbase] = qv.z;
        sQ[(d4 + 3) * APITCH + cbase] = qv.w;
    }

    float m_i[4], l_i[4], o[4][4];
    #pragma unroll
    for (int i = 0; i < 4; i++) {
        m_i[i] = -1e30f; l_i[i] = 0.f;
        #pragma unroll
        for (int j = 0; j < 4; j++) o[i][j] = 0.f;
    }

    for (int kt = 0; kt < 16; kt++) {
        __syncthreads();   // protect sK/sV/sS from prior-iter readers; sQ from loaders (iter 0)

        // ---- load K tile transposed(+swizzle) and V tile natural ----
        #pragma unroll
        for (int it = 0; it < 4; it++) {
            int idx = tid + it * 256;
            int r = idx >> 4;
            int d4 = (idx & 15) << 2;
            size_t goff = base + (size_t)(kt * 64 + r) * DD + d4;
            float4 kv = *(const float4*)(Kf + goff);
            float4 vv = *(const float4*)(V + goff);
            int sw = ((d4 >> 2) & 7) << 2;
            int cbase = (((r >> 2) << 2) ^ sw) + (r & 3);
            sK[(d4 + 0) * APITCH + cbase] = kv.x;
            sK[(d4 + 1) * APITCH + cbase] = kv.y;
            sK[(d4 + 2) * APITCH + cbase] = kv.z;
            sK[(d4 + 3) * APITCH + cbase] = kv.w;
            *(float4*)&sV[r * APITCH + d4] = vv;
        }
        __syncthreads();

        // ---- S tile: s[i][j] = sum_d Q[q][d] K[k][d],  q=q0+ty*4+i, k=kt*64+tx*4+j
        float s[4][4] = {};
        #pragma unroll 16
        for (int d = 0; d < 64; d++) {
            int sw = ((d >> 2) & 7) << 2;
            float4 a  = *(float4*)&sQ[d * APITCH + ((ty << 2) ^ sw)];
            float4 bq = *(float4*)&sK[d * APITCH + ((tx << 2) ^ sw)];
            float av[4] = {a.x, a.y, a.z, a.w};
            float bv[4] = {bq.x, bq.y, bq.z, bq.w};
            #pragma unroll
            for (int i = 0; i < 4; i++)
                #pragma unroll
                for (int j = 0; j < 4; j++)
                    s[i][j] += av[i] * bv[j];
        }

        // ---- online softmax update (rows owned by ty-group; reduce over 16 tx lanes)
        #pragma unroll
        for (int i = 0; i < 4; i++) {
            #pragma unroll
            for (int j = 0; j < 4; j++) s[i][j] *= 0.125f;   // 1/sqrt(64)
            float tm = fmaxf(fmaxf(s[i][0], s[i][1]), fmaxf(s[i][2], s[i][3]));
            #pragma unroll
            for (int off = 8; off > 0; off >>= 1)
                tm = fmaxf(tm, __shfl_xor_sync(0xffffffffu, tm, off));
            float mn = fmaxf(m_i[i], tm);
            float f = expf(m_i[i] - mn);
            m_i[i] = mn;
            l_i[i] *= f;
            #pragma unroll
            for (int j = 0; j < 4; j++) o[i][j] *= f;
            float rs = 0.f;
            #pragma unroll
            for (int j = 0; j < 4; j++) {
                float p = expf(s[i][j] - mn);
                s[i][j] = p; rs += p;
            }
            #pragma unroll
            for (int off = 8; off > 0; off >>= 1)
                rs += __shfl_xor_sync(0xffffffffu, rs, off);
            l_i[i] += rs;
        }

        // ---- stage P transposed (+swizzle): sS[j][q]
        {
            int sw = (tx & 7) << 2;                 // (j>>2)&7 == tx for j=tx*4+jj
            int cb = ((ty << 2) ^ sw);
            #pragma unroll
            for (int jj = 0; jj < 4; jj++)
                #pragma unroll
                for (int ii = 0; ii < 4; ii++)
                    sS[(tx * 4 + jj) * APITCH + cb + ii] = s[ii][jj];
        }
        __syncthreads();

        // ---- O += P V
        #pragma unroll 16
        for (int j = 0; j < 64; j++) {
            int sw = ((j >> 2) & 7) << 2;
            float4 a  = *(float4*)&sS[j * APITCH + ((ty << 2) ^ sw)];
            float4 bv = *(float4*)&sV[j * APITCH + (tx << 2)];
            float av[4] = {a.x, a.y, a.z, a.w};
            float vv[4] = {bv.x, bv.y, bv.z, bv.w};
            #pragma unroll
            for (int i = 0; i < 4; i++)
                #pragma unroll
                for (int k = 0; k < 4; k++)
                    o[i][k] += av[i] * vv[k];
        }
    }

    // ---- epilogue: normalize + store
    #pragma unroll
    for (int i = 0; i < 4; i++) {
        float inv = 1.f / l_i[i];
        float4 ov = make_float4(o[i][0] * inv, o[i][1] * inv,
                                o[i][2] * inv, o[i][3] * inv);
        *(float4*)(O + base + (size_t)(q0 + ty * 4 + i) * DD + (tx << 2)) = ov;
    }
}

// ------------------------- residual + layernorm -----------------------------
__global__ __launch_bounds__(256) void lnres_kernel(
    float* __restrict__ Hb, const float* __restrict__ R,
    const float* __restrict__ gam, const float* __restrict__ bet)
{
    int token = (blockIdx.x << 3) + (threadIdx.x >> 5);
    int lane  = threadIdx.x & 31;
    float* hr = Hb + (size_t)token * DD;
    const float* rr = R + (size_t)token * DD;

    float vals[8];
    float s = 0.f;
    #pragma unroll
    for (int t = 0; t < 8; t++) {
        float v = hr[lane + (t << 5)] + rr[lane + (t << 5)];
        vals[t] = v; s += v;
    }
    #pragma unroll
    for (int o = 16; o > 0; o >>= 1) s += __shfl_xor_sync(~0u, s, o);
    float mean = s * (1.f / 256.f);
    float vs = 0.f;
    #pragma unroll
    for (int t = 0; t < 8; t++) { float d = vals[t] - mean; vs += d * d; }
    #pragma unroll
    for (int o = 16; o > 0; o >>= 1) vs += __shfl_xor_sync(~0u, vs, o);
    float inv = 1.f / sqrtf(vs * (1.f / 256.f) + 1e-5f);
    #pragma unroll
    for (int t = 0; t < 8; t++) {
        int d = lane + (t << 5);
        hr[d] = (vals[t] - mean) * inv * gam[d] + bet[d];
    }
}

// ------------------------------- mean over N --------------------------------
__global__ void mean_kernel(const float* __restrict__ H, float* __restrict__ Hm)
{
    int b = blockIdx.x, d = threadIdx.x;
    const float* p = H + (size_t)b * NNQ * DD + d;
    float s = 0.f;
    for (int n = 0; n < NNQ; n++) s += p[(size_t)n * DD];
    Hm[b * DD + d] = s * (1.f / 1024.f);
}

// ---------------- scores + gumbel-softmax weights (per batch b) -------------
__global__ __launch_bounds__(256) void score_kernel(
    const float* __restrict__ QV, const float* __restrict__ KV,
    const float* __restrict__ gum, float* __restrict__ outw)
{
    __shared__ float sqv[256];
    __shared__ float ss[1024];
    __shared__ float red[8];
    int b = blockIdx.x, tid = threadIdx.x;
    int wid = tid >> 5, lane = tid & 31;

    sqv[tid] = QV[b * 256 + tid];
    __syncthreads();

    for (int n = wid; n < 1024; n += 8) {
        const float* kr = KV + ((size_t)b * NNQ + n) * DD;
        float s = 0.f;
        #pragma unroll
        for (int t = 0; t < 8; t++) s += sqv[lane + (t << 5)] * kr[lane + (t << 5)];
        #pragma unroll
        for (int o = 16; o > 0; o >>= 1) s += __shfl_xor_sync(~0u, s, o);
        if (lane == 0) ss[n] = (s * 0.0625f + gum[b * NNQ + n]) * 2.0f;
    }
    __syncthreads();

    float mx = -1e30f;
    for (int c = tid; c < 1024; c += 256) mx = fmaxf(mx, ss[c]);
    #pragma unroll
    for (int o = 16; o > 0; o >>= 1) mx = fmaxf(mx, __shfl_xor_sync(~0u, mx, o));
    if (lane == 0) red[wid] = mx;
    __syncthreads();
    float bm = -1e30f;
    #pragma unroll
    for (int i = 0; i < 8; i++) bm = fmaxf(bm, red[i]);
    __syncthreads();

    float sum = 0.f;
    for (int c = tid; c < 1024; c += 256) {
        float e = expf(ss[c] - bm); ss[c] = e; sum += e;
    }
    #pragma unroll
    for (int o = 16; o > 0; o >>= 1) sum += __shfl_xor_sync(~0u, sum, o);
    if (lane == 0) red[wid] = sum;
    __syncthreads();
    float tot = 0.f;
    #pragma unroll
    for (int i = 0; i < 8; i++) tot += red[i];
    float inv = 1.f / tot;
    for (int c = tid; c < 1024; c += 256)
        outw[b * NNQ + c] = ss[c] * inv;
}

// ------------------------- top-k via bitonic sort ---------------------------
__global__ __launch_bounds__(512) void topk_kernel(
    const float* __restrict__ Wts, int* __restrict__ idx_out,
    float* __restrict__ idxf_out)
{
    __shared__ float sv[1024];
    __shared__ int   si[1024];
    int b = blockIdx.x, tid = threadIdx.x;
    for (int i = tid; i < 1024; i += 512) { sv[i] = Wts[b * 1024 + i]; si[i] = i; }
    __syncthreads();
    for (int k = 2; k <= 1024; k <<= 1) {
        for (int j = k >> 1; j > 0; j >>= 1) {
            for (int i = tid; i < 1024; i += 512) {
                int ix = i ^ j;
                if (ix > i) {
                    bool up = ((i & k) == 0);
                    float v1 = sv[i], v2 = sv[ix];
                    int   i1 = si[i], i2 = si[ix];
                    bool before = (v1 > v2) || (v1 == v2 && i1 < i2);
                    if (up ? !before : before) {
                        sv[i] = v2; sv[ix] = v1;
                        si[i] = i2; si[ix] = i1;
                    }
                }
            }
            __syncthreads();
        }
    }
    if (tid < KKK) {
        idx_out[b * KKK + tid]  = si[tid];
        idxf_out[b * KKK + tid] = (float)si[tid];
    }
}

// --------------------- alloc softmax + gather + renorm ----------------------
__global__ __launch_bounds__(256) void sel_kernel(
    const float* __restrict__ logits, const int* __restrict__ tk,
    float* __restrict__ sel_out)
{
    __shared__ float sl[1024];
    __shared__ float red[8];
    __shared__ float ssum;
    int b = blockIdx.x, tid = threadIdx.x;
    int wid = tid >> 5, lane = tid & 31;

    for (int c = tid; c < 1024; c += 256) sl[c] = logits[b * 1024 + c];
    __syncthreads();

    float mx = -1e30f;
    for (int c = tid; c < 1024; c += 256) mx = fmaxf(mx, sl[c]);
    #pragma unroll
    for (int o = 16; o > 0; o >>= 1) mx = fmaxf(mx, __shfl_xor_sync(~0u, mx, o));
    if (lane == 0) red[wid] = mx;
    __syncthreads();
    float bm = -1e30f;
    #pragma unroll
    for (int i = 0; i < 8; i++) bm = fmaxf(bm, red[i]);
    __syncthreads();

    float sum = 0.f;
    for (int c = tid; c < 1024; c += 256) {
        float e = expf(sl[c] - bm); sl[c] = e; sum += e;
    }
    #pragma unroll
    for (int o = 16; o > 0; o >>= 1) sum += __shfl_xor_sync(~0u, sum, o);
    if (lane == 0) red[wid] = sum;
    __syncthreads();
    float tot = 0.f;
    #pragma unroll
    for (int i = 0; i < 8; i++) tot += red[i];
    float inv = 1.f / tot;
    __syncthreads();
    for (int c = tid; c < 1024; c += 256) sl[c] *= inv;
    __syncthreads();

    if (tid == 0) {
        float s = 0.f;
        for (int kk = 0; kk < KKK; kk++) s += sl[tk[b * KKK + kk]];
        ssum = s;
    }
    __syncthreads();
    if (tid < KKK) {
        float v = sl[tk[b * KKK + tid]];
        sel_out[b * KKK + tid] = v / (ssum + 1e-12f);
    }
}

// ------------------------------- launcher -----------------------------------
static inline void launch_gemm(const float* A, const float* W, const float* bias,
                               float* C, int M, int N, int Kd, int relu)
{
    if ((M % 128 == 0) && (N % 128 == 0) && (Kd % 16 == 0)) {
        dim3 grid(N / 128, M / 128);
        gemm128_kernel<<<grid, 256>>>(A, W, bias, C, M, N, Kd, relu);
    } else {
        dim3 grid(N / 64, M / 64);
        gemm_kernel<<<grid, 256>>>(A, W, bias, C, M, N, Kd, relu);
    }
}

extern "C" void kernel_launch(void* const* d_in, const int* in_sizes, int n_in,
                              void* d_out, int out_size)
{
    const float* x      = (const float*)d_in[0];
    const float* gumbel = (const float*)d_in[1];
    const float* emb_W  = (const float*)d_in[2];
    const float* emb_b  = (const float*)d_in[3];
    const float* Wq     = (const float*)d_in[4];
    const float* Wk     = (const float*)d_in[5];
    const float* Wv     = (const float*)d_in[6];
    const float* Wo     = (const float*)d_in[7];
    const float* ln1_g  = (const float*)d_in[8];
    const float* ln1_b  = (const float*)d_in[9];
    const float* ln2_g  = (const float*)d_in[10];
    const float* ln2_b  = (const float*)d_in[11];
    const float* ffn_W1 = (const float*)d_in[12];
    const float* ffn_b1 = (const float*)d_in[13];
    const float* ffn_W2 = (const float*)d_in[14];
    const float* ffn_b2 = (const float*)d_in[15];
    const float* sha_Wq = (const float*)d_in[16];
    const float* sha_Wk = (const float*)d_in[17];
    const float* aW1    = (const float*)d_in[18];
    const float* ab1    = (const float*)d_in[19];
    const float* aW2    = (const float*)d_in[20];
    const float* ab2    = (const float*)d_in[21];

    float* out     = (float*)d_out;
    float* out_w   = out;                  // [64*1024]
    float* out_idx = out + BB * NNQ;       // [64*64] indices as float
    float* out_sel = out_idx + BB * KKK;   // [64*64]

    float *ph, *pq, *pk, *pv, *po, *pffn, *phm, *pqv, *pt1, *plog;
    int* ptk;
    cudaGetSymbolAddress((void**)&ph,   g_h);
    cudaGetSymbolAddress((void**)&pq,   g_q);
    cudaGetSymbolAddress((void**)&pk,   g_k);
    cudaGetSymbolAddress((void**)&pv,   g_v);
    cudaGetSymbolAddress((void**)&po,   g_o);
    cudaGetSymbolAddress((void**)&pffn, g_ffn);
    cudaGetSymbolAddress((void**)&phm,  g_hmean);
    cudaGetSymbolAddress((void**)&pqv,  g_qv);
    cudaGetSymbolAddress((void**)&pt1,  g_t1);
    cudaGetSymbolAddress((void**)&plog, g_logits);
    cudaGetSymbolAddress((void**)&ptk,  g_topk);

    size_t attn_smem = (size_t)FATTN_SMEM_FLOATS * sizeof(float);   // 69632 B
    cudaFuncSetAttribute(fattn_kernel, cudaFuncAttributeMaxDynamicSharedMemorySize,
                         (int)attn_smem);

    // embed: h = x @ emb_W + emb_b
    launch_gemm(x, emb_W, emb_b, ph, TOK, DD, DIN, 0);

    for (int i = 0; i < LLL; i++) {
        const float* wq = Wq + (size_t)i * DD * DD;
        const float* wk = Wk + (size_t)i * DD * DD;
        const float* wv = Wv + (size_t)i * DD * DD;
        const float* wo = Wo + (size_t)i * DD * DD;

        launch_gemm(ph, wq, nullptr, pq, TOK, DD, DD, 0);
        launch_gemm(ph, wk, nullptr, pk, TOK, DD, DD, 0);
        launch_gemm(ph, wv, nullptr, pv, TOK, DD, DD, 0);

        fattn_kernel<<<dim3(NNQ / 64, BB * HH), 256, attn_smem>>>(pq, pk, pv, po);

        launch_gemm(po, wo, nullptr, pq, TOK, DD, DD, 0);
        lnres_kernel<<<TOK / 8, 256>>>(ph, pq, ln1_g + i * DD, ln1_b + i * DD);

        launch_gemm(ph, ffn_W1 + (size_t)i * DD * DFFN, ffn_b1 + i * DFFN,
                    pffn, TOK, DFFN, DD, 1);
        launch_gemm(pffn, ffn_W2 + (size_t)i * DFFN * DD, ffn_b2 + i * DD,
                    pq, TOK, DD, DFFN, 0);
        lnres_kernel<<<TOK / 8, 256>>>(ph, pq, ln2_g + i * DD, ln2_b + i * DD);
    }

    // head
    mean_kernel<<<BB, DD>>>(ph, phm);
    launch_gemm(phm, sha_Wq, nullptr, pqv, BB, DD, DD, 0);   // qv  [64,256]
    launch_gemm(ph, sha_Wk, nullptr, pk, TOK, DD, DD, 0);    // kv  [65536,256]

    score_kernel<<<BB, 256>>>(pqv, pk, gumbel, out_w);
    topk_kernel<<<BB, 512>>>(out_w, ptk, out_idx);

    launch_gemm(phm, aW1, ab1, pt1, BB, DD, DD, 1);          // relu(hmean@W1+b1)
    launch_gemm(pt1, aW2, ab2, plog, BB, NNQ, DD, 0);        // logits [64,1024]
    sel_kernel<<<BB, 256>>>(plog, ptk, out_sel);
}

// round 9
// speedup vs baseline: 2.0436x; 1.0236x over previous
#include <cuda_runtime.h>
#include <cstdint>

// ---------------------------------------------------------------------------
// ContActor: B=64, N=1024, D_IN=16, D=256, H=4, DH=64, L=3, DFF=1024, K=64
// Full fp32. Outputs (concatenated float32):
//   weights [64*1024], topk_idx (as float) [64*64], sel [64*64]
// Round 9: round-8 kernel + missing <cstdint> include (compile fix only).
// gemm128 pipelined: BK=32, B via cp.async, dynamic smem, launch_bounds(256,2).
// fattn + everything else unchanged from the round-7 WIN (13146us).
// ---------------------------------------------------------------------------

#define BB   64
#define NNQ  1024
#define DIN  16
#define DD   256
#define HH   4
#define DHH  64
#define LLL  3
#define DFFN 1024
#define KKK  64
#define TOK  (BB * NNQ)   // 65536

// ------------------------- scratch (device globals) ------------------------
__device__ float g_h  [(size_t)TOK * DD];
__device__ float g_q  [(size_t)TOK * DD];
__device__ float g_k  [(size_t)TOK * DD];
__device__ float g_v  [(size_t)TOK * DD];
__device__ float g_o  [(size_t)TOK * DD];
__device__ float g_ffn[(size_t)TOK * DFFN];
__device__ float g_hmean[BB * DD];
__device__ float g_qv   [BB * DD];
__device__ float g_t1   [BB * DD];
__device__ float g_logits[BB * NNQ];
__device__ int   g_topk  [BB * KKK];

// --------------------- big GEMM: 128x128 tile, BK=32, 8x8 micro -------------
// C[M,N] = A[M,Kd] @ W[Kd,N] (+bias)(+relu). Requires M%128==0, N%128==0,
// Kd%32==0. Double-buffered: A via register prefetch + transposed STS,
// B via cp.async straight into smem. One barrier per 32-k tile.
#define BM 128
#define BN 128
#define BK 32
#define APS 132                         // As row pitch (floats)
#define G128_SMEM_FLOATS (2 * BK * APS + 2 * BK * BN)   // 8448 + 8192

__global__ __launch_bounds__(256, 2) void gemm128_kernel(
    const float* __restrict__ A, const float* __restrict__ W,
    const float* __restrict__ bias, float* __restrict__ C,
    int M, int N, int Kd, int do_relu)
{
    extern __shared__ float gsm[];
    float* As = gsm;                     // [2][BK][APS]  (k-major, m inner)
    float* Bs = gsm + 2 * BK * APS;      // [2][BK][BN]

    int tid = threadIdx.x;
    int m0 = blockIdx.y * BM, n0 = blockIdx.x * BN;

    int ar = tid >> 1;                  // 0..127 (A row)
    int ac = (tid & 1) << 4;            // 0 or 16 (A k-offset)
    int brow = tid >> 5;                // 0..7   (B row base)
    int bcol = (tid & 31) << 2;         // 0..124 (B col, 16B chunks)
    int tx = tid & 15, ty = tid >> 4;

    const int nt = Kd / BK;

    float acc[8][8] = {};
    float4 pa[4];

    uint32_t bs_base;
    asm("{ .reg .u64 t; cvta.to.shared.u64 t, %1; cvt.u32.u64 %0, t; }"
        : "=r"(bs_base) : "l"(Bs));

    // ---- prologue: stage 0 ----
    {
        const float* ap = A + (size_t)(m0 + ar) * Kd + ac;
        #pragma unroll
        for (int i = 0; i < 4; i++) pa[i] = *(const float4*)(ap + 4 * i);
        #pragma unroll
        for (int p = 0; p < 4; p++) {
            int r = brow + p * 8;
            uint32_t dst = bs_base + (uint32_t)((r * BN + bcol) * 4);
            const float* src = W + (size_t)r * N + n0 + bcol;
            asm volatile("cp.async.cg.shared.global [%0], [%1], 16;\n"
                         :: "r"(dst), "l"(src));
        }
        asm volatile("cp.async.commit_group;\n" ::: "memory");
        #pragma unroll
        for (int i = 0; i < 4; i++) {
            As[(ac + 4 * i + 0) * APS + ar] = pa[i].x;
            As[(ac + 4 * i + 1) * APS + ar] = pa[i].y;
            As[(ac + 4 * i + 2) * APS + ar] = pa[i].z;
            As[(ac + 4 * i + 3) * APS + ar] = pa[i].w;
        }
        asm volatile("cp.async.wait_group 0;\n" ::: "memory");
        __syncthreads();
    }

    for (int kt = 0; kt < nt; kt++) {
        int cur = kt & 1, nxt = cur ^ 1;

        // issue next stage (B async, A into regs) — overlaps compute below
        if (kt + 1 < nt) {
            int k0 = (kt + 1) * BK;
            const float* ap = A + (size_t)(m0 + ar) * Kd + k0 + ac;
            #pragma unroll
            for (int i = 0; i < 4; i++) pa[i] = *(const float4*)(ap + 4 * i);
            #pragma unroll
            for (int p = 0; p < 4; p++) {
                int r = brow + p * 8;
                uint32_t dst = bs_base + (uint32_t)(((nxt * BK + r) * BN + bcol) * 4);
                const float* src = W + (size_t)(k0 + r) * N + n0 + bcol;
                asm volatile("cp.async.cg.shared.global [%0], [%1], 16;\n"
                             :: "r"(dst), "l"(src));
            }
            asm volatile("cp.async.commit_group;\n" ::: "memory");
        }

        // compute current stage
        const float* Asc = As + cur * BK * APS;
        const float* Bsc = Bs + cur * BK * BN;
        #pragma unroll
        for (int k = 0; k < BK; k++) {
            float a[8], b[8];
            *(float4*)&a[0] = *(const float4*)&Asc[k * APS + ty * 8];
            *(float4*)&a[4] = *(const float4*)&Asc[k * APS + ty * 8 + 4];
            *(float4*)&b[0] = *(const float4*)&Bsc[k * BN + tx * 8];
            *(float4*)&b[4] = *(const float4*)&Bsc[k * BN + tx * 8 + 4];
            #pragma unroll
            for (int i = 0; i < 8; i++)
                #pragma unroll
                for (int j = 0; j < 8; j++)
                    acc[i][j] += a[i] * b[j];
        }

        // drain stage kt+1 into smem, wait for B, barrier
        if (kt + 1 < nt) {
            float* Asn = As + nxt * BK * APS;
            #pragma unroll
            for (int i = 0; i < 4; i++) {
                Asn[(ac + 4 * i + 0) * APS + ar] = pa[i].x;
                Asn[(ac + 4 * i + 1) * APS + ar] = pa[i].y;
                Asn[(ac + 4 * i + 2) * APS + ar] = pa[i].z;
                Asn[(ac + 4 * i + 3) * APS + ar] = pa[i].w;
            }
            asm volatile("cp.async.wait_group 0;\n" ::: "memory");
        }
        __syncthreads();
    }

    // epilogue
    #pragma unroll
    for (int i = 0; i < 8; i++) {
        float* crow = C + (size_t)(m0 + ty * 8 + i) * N + n0 + tx * 8;
        #pragma unroll
        for (int j4 = 0; j4 < 8; j4 += 4) {
            float4 o;
            float* po = (float*)&o;
            #pragma unroll
            for (int j = 0; j < 4; j++) {
                float v = acc[i][j4 + j];
                if (bias) v += bias[n0 + tx * 8 + j4 + j];
                if (do_relu) v = fmaxf(v, 0.f);
                po[j] = v;
            }
            *(float4*)(crow + j4) = o;
        }
    }
}

// --------------------- small GEMM: 64x64 tile, BK=32, 4x4 micro --------------
__global__ __launch_bounds__(256) void gemm_kernel(
    const float* __restrict__ A, const float* __restrict__ W,
    const float* __restrict__ bias, float* __restrict__ C,
    int M, int N, int Kd, int do_relu)
{
    __shared__ float As[64][36];
    __shared__ float Bs[32][64];
    int tid = threadIdx.x;
    int tx = tid & 15, ty = tid >> 4;
    int m0 = blockIdx.y << 6, n0 = blockIdx.x << 6;

    float acc[4][4] = {};

    for (int k0 = 0; k0 < Kd; k0 += 32) {
        {
            int r  = tid >> 3;
            int c4 = (tid & 7) << 2;
            #pragma unroll
            for (int rr = 0; rr < 64; rr += 32) {
                float4 val;
                if (k0 + c4 < Kd)
                    val = *(const float4*)(A + (size_t)(m0 + r + rr) * Kd + k0 + c4);
                else
                    val = make_float4(0.f, 0.f, 0.f, 0.f);
                *(float4*)&As[r + rr][c4] = val;
            }
        }
        {
            int r  = tid >> 4;
            int c4 = (tid & 15) << 2;
            #pragma unroll
            for (int rr = 0; rr < 32; rr += 16) {
                float4 val;
                if (k0 + r + rr < Kd)
                    val = *(const float4*)(W + (size_t)(k0 + r + rr) * N + n0 + c4);
                else
                    val = make_float4(0.f, 0.f, 0.f, 0.f);
                *(float4*)&Bs[r + rr][c4] = val;
            }
        }
        __syncthreads();
        #pragma unroll
        for (int k = 0; k < 32; k++) {
            float4 bv = *(float4*)&Bs[k][tx << 2];
            float b[4] = {bv.x, bv.y, bv.z, bv.w};
            float a[4];
            #pragma unroll
            for (int i = 0; i < 4; i++) a[i] = As[(ty << 2) + i][k];
            #pragma unroll
            for (int i = 0; i < 4; i++)
                #pragma unroll
                for (int j = 0; j < 4; j++)
                    acc[i][j] += a[i] * b[j];
        }
        __syncthreads();
    }

    #pragma unroll
    for (int i = 0; i < 4; i++) {
        float4 out;
        float* po = (float*)&out;
        #pragma unroll
        for (int j = 0; j < 4; j++) {
            float v = acc[i][j];
            if (bias) v += bias[n0 + (tx << 2) + j];
            if (do_relu) v = fmaxf(v, 0.f);
            po[j] = v;
        }
        *(float4*)(C + (size_t)(m0 + (ty << 2) + i) * N + n0 + (tx << 2)) = out;
    }
}

// ---------------------- flash attention (64q x 64k tiles) -------------------
#define APITCH 68   // floats per row (64 + 4 pad), 272B (16B aligned)
#define FATTN_SMEM_FLOATS (4 * 64 * APITCH)

__global__ __launch_bounds__(256, 2) void fattn_kernel(
    const float* __restrict__ Q, const float* __restrict__ Kf,
    const float* __restrict__ V, float* __restrict__ O)
{
    extern __shared__ float sm[];
    float* sQ = sm;                      // [d][q] swizzled
    float* sK = sQ + 64 * APITCH;        // [d][k] swizzled
    float* sV = sK + 64 * APITCH;        // [j][d] natural
    float* sS = sV + 64 * APITCH;        // [j][q] swizzled

    int tid = threadIdx.x;
    int tx = tid & 15, ty = tid >> 4;
    int bh = blockIdx.y;
    int b  = bh >> 2, h = bh & 3;
    int q0 = blockIdx.x << 6;
    size_t base = ((size_t)b * NNQ) * DD + h * DHH;

    // ---- load Q tile transposed ----
    #pragma unroll
    for (int it = 0; it < 4; it++) {
        int idx = tid + it * 256;
        int r = idx >> 4;            // 0..63
        int d4 = (idx & 15) << 2;    // 0..60
        float4 qv = *(const float4*)(Q + base + (size_t)(q0 + r) * DD + d4);
        int sw = ((d4 >> 2) & 7) << 2;
        int cbase = (((r >> 2) << 2) ^ sw) + (r & 3);
        sQ[(d4 + 0) * APITCH + cbase] = qv.x;
        sQ[(d4 + 1) * APITCH + cbase] = qv.y;
        sQ[(d4 + 2) * APITCH + cbase] = qv.z;
        sQ[(d4 + 3) * APITCH + cbase] = qv.w;
    }

    float m_i[4], l_i[4], o[4][4];
    #pragma unroll
    for (int i = 0; i < 4; i++) {
        m_i[i] = -1e30f; l_i[i] = 0.f;
        #pragma unroll
        for (int j = 0; j < 4; j++) o[i][j] = 0.f;
    }

    for (int kt = 0; kt < 16; kt++) {
        __syncthreads();

        // ---- load K tile transposed(+swizzle) and V tile natural ----
        #pragma unroll
        for (int it = 0; it < 4; it++) {
            int idx = tid + it * 256;
            int r = idx >> 4;
            int d4 = (idx & 15) << 2;
            size_t goff = base + (size_t)(kt * 64 + r) * DD + d4;
            float4 kv = *(const float4*)(Kf + goff);
            float4 vv = *(const float4*)(V + goff);
            int sw = ((d4 >> 2) & 7) << 2;
            int cbase = (((r >> 2) << 2) ^ sw) + (r & 3);
            sK[(d4 + 0) * APITCH + cbase] = kv.x;
            sK[(d4 + 1) * APITCH + cbase] = kv.y;
            sK[(d4 + 2) * APITCH + cbase] = kv.z;
            sK[(d4 + 3) * APITCH + cbase] = kv.w;
            *(float4*)&sV[r * APITCH + d4] = vv;
        }
        __syncthreads();

        // ---- S tile
        float s[4][4] = {};
        #pragma unroll 16
        for (int d = 0; d < 64; d++) {
            int sw = ((d >> 2) & 7) << 2;
            float4 a  = *(float4*)&sQ[d * APITCH + ((ty << 2) ^ sw)];
            float4 bq = *(float4*)&sK[d * APITCH + ((tx << 2) ^ sw)];
            float av[4] = {a.x, a.y, a.z, a.w};
            float bv[4] = {bq.x, bq.y, bq.z, bq.w};
            #pragma unroll
            for (int i = 0; i < 4; i++)
                #pragma unroll
                for (int j = 0; j < 4; j++)
                    s[i][j] += av[i] * bv[j];
        }

        // ---- online softmax update
        #pragma unroll
        for (int i = 0; i < 4; i++) {
            #pragma unroll
            for (int j = 0; j < 4; j++) s[i][j] *= 0.125f;
            float tm = fmaxf(fmaxf(s[i][0], s[i][1]), fmaxf(s[i][2], s[i][3]));
            #pragma unroll
            for (int off = 8; off > 0; off >>= 1)
                tm = fmaxf(tm, __shfl_xor_sync(0xffffffffu, tm, off));
            float mn = fmaxf(m_i[i], tm);
            float f = expf(m_i[i] - mn);
            m_i[i] = mn;
            l_i[i] *= f;
            #pragma unroll
            for (int j = 0; j < 4; j++) o[i][j] *= f;
            float rs = 0.f;
            #pragma unroll
            for (int j = 0; j < 4; j++) {
                float p = expf(s[i][j] - mn);
                s[i][j] = p; rs += p;
            }
            #pragma unroll
            for (int off = 8; off > 0; off >>= 1)
                rs += __shfl_xor_sync(0xffffffffu, rs, off);
            l_i[i] += rs;
        }

        // ---- stage P transposed (+swizzle)
        {
            int sw = (tx & 7) << 2;
            int cb = ((ty << 2) ^ sw);
            #pragma unroll
            for (int jj = 0; jj < 4; jj++)
                #pragma unroll
                for (int ii = 0; ii < 4; ii++)
                    sS[(tx * 4 + jj) * APITCH + cb + ii] = s[ii][jj];
        }
        __syncthreads();

        // ---- O += P V
        #pragma unroll 16
        for (int j = 0; j < 64; j++) {
            int sw = ((j >> 2) & 7) << 2;
            float4 a  = *(float4*)&sS[j * APITCH + ((ty << 2) ^ sw)];
            float4 bv = *(float4*)&sV[j * APITCH + (tx << 2)];
            float av[4] = {a.x, a.y, a.z, a.w};
            float vv[4] = {bv.x, bv.y, bv.z, bv.w};
            #pragma unroll
            for (int i = 0; i < 4; i++)
                #pragma unroll
                for (int k = 0; k < 4; k++)
                    o[i][k] += av[i] * vv[k];
        }
    }

    // ---- epilogue
    #pragma unroll
    for (int i = 0; i < 4; i++) {
        float inv = 1.f / l_i[i];
        float4 ov = make_float4(o[i][0] * inv, o[i][1] * inv,
                                o[i][2] * inv, o[i][3] * inv);
        *(float4*)(O + base + (size_t)(q0 + ty * 4 + i) * DD + (tx << 2)) = ov;
    }
}

// ------------------------- residual + layernorm -----------------------------
__global__ __launch_bounds__(256) void lnres_kernel(
    float* __restrict__ Hb, const float* __restrict__ R,
    const float* __restrict__ gam, const float* __restrict__ bet)
{
    int token = (blockIdx.x << 3) + (threadIdx.x >> 5);
    int lane  = threadIdx.x & 31;
    float* hr = Hb + (size_t)token * DD;
    const float* rr = R + (size_t)token * DD;

    float vals[8];
    float s = 0.f;
    #pragma unroll
    for (int t = 0; t < 8; t++) {
        float v = hr[lane + (t << 5)] + rr[lane + (t << 5)];
        vals[t] = v; s += v;
    }
    #pragma unroll
    for (int o = 16; o > 0; o >>= 1) s += __shfl_xor_sync(~0u, s, o);
    float mean = s * (1.f / 256.f);
    float vs = 0.f;
    #pragma unroll
    for (int t = 0; t < 8; t++) { float d = vals[t] - mean; vs += d * d; }
    #pragma unroll
    for (int o = 16; o > 0; o >>= 1) vs += __shfl_xor_sync(~0u, vs, o);
    float inv = 1.f / sqrtf(vs * (1.f / 256.f) + 1e-5f);
    #pragma unroll
    for (int t = 0; t < 8; t++) {
        int d = lane + (t << 5);
        hr[d] = (vals[t] - mean) * inv * gam[d] + bet[d];
    }
}

// ------------------------------- mean over N --------------------------------
__global__ void mean_kernel(const float* __restrict__ H, float* __restrict__ Hm)
{
    int b = blockIdx.x, d = threadIdx.x;
    const float* p = H + (size_t)b * NNQ * DD + d;
    float s = 0.f;
    for (int n = 0; n < NNQ; n++) s += p[(size_t)n * DD];
    Hm[b * DD + d] = s * (1.f / 1024.f);
}

// ---------------- scores + gumbel-softmax weights (per batch b) -------------
__global__ __launch_bounds__(256) void score_kernel(
    const float* __restrict__ QV, const float* __restrict__ KV,
    const float* __restrict__ gum, float* __restrict__ outw)
{
    __shared__ float sqv[256];
    __shared__ float ss[1024];
    __shared__ float red[8];
    int b = blockIdx.x, tid = threadIdx.x;
    int wid = tid >> 5, lane = tid & 31;

    sqv[tid] = QV[b * 256 + tid];
    __syncthreads();

    for (int n = wid; n < 1024; n += 8) {
        const float* kr = KV + ((size_t)b * NNQ + n) * DD;
        float s = 0.f;
        #pragma unroll
        for (int t = 0; t < 8; t++) s += sqv[lane + (t << 5)] * kr[lane + (t << 5)];
        #pragma unroll
        for (int o = 16; o > 0; o >>= 1) s += __shfl_xor_sync(~0u, s, o);
        if (lane == 0) ss[n] = (s * 0.0625f + gum[b * NNQ + n]) * 2.0f;
    }
    __syncthreads();

    float mx = -1e30f;
    for (int c = tid; c < 1024; c += 256) mx = fmaxf(mx, ss[c]);
    #pragma unroll
    for (int o = 16; o > 0; o >>= 1) mx = fmaxf(mx, __shfl_xor_sync(~0u, mx, o));
    if (lane == 0) red[wid] = mx;
    __syncthreads();
    float bm = -1e30f;
    #pragma unroll
    for (int i = 0; i < 8; i++) bm = fmaxf(bm, red[i]);
    __syncthreads();

    float sum = 0.f;
    for (int c = tid; c < 1024; c += 256) {
        float e = expf(ss[c] - bm); ss[c] = e; sum += e;
    }
    #pragma unroll
    for (int o = 16; o > 0; o >>= 1) sum += __shfl_xor_sync(~0u, sum, o);
    if (lane == 0) red[wid] = sum;
    __syncthreads();
    float tot = 0.f;
    #pragma unroll
    for (int i = 0; i < 8; i++) tot += red[i];
    float inv = 1.f / tot;
    for (int c = tid; c < 1024; c += 256)
        outw[b * NNQ + c] = ss[c] * inv;
}

// ------------------------- top-k via bitonic sort ---------------------------
__global__ __launch_bounds__(512) void topk_kernel(
    const float* __restrict__ Wts, int* __restrict__ idx_out,
    float* __restrict__ idxf_out)
{
    __shared__ float sv[1024];
    __shared__ int   si[1024];
    int b = blockIdx.x, tid = threadIdx.x;
    for (int i = tid; i < 1024; i += 512) { sv[i] = Wts[b * 1024 + i]; si[i] = i; }
    __syncthreads();
    for (int k = 2; k <= 1024; k <<= 1) {
        for (int j = k >> 1; j > 0; j >>= 1) {
            for (int i = tid; i < 1024; i += 512) {
                int ix = i ^ j;
                if (ix > i) {
                    bool up = ((i & k) == 0);
                    float v1 = sv[i], v2 = sv[ix];
                    int   i1 = si[i], i2 = si[ix];
                    bool before = (v1 > v2) || (v1 == v2 && i1 < i2);
                    if (up ? !before : before) {
                        sv[i] = v2; sv[ix] = v1;
                        si[i] = i2; si[ix] = i1;
                    }
                }
            }
            __syncthreads();
        }
    }
    if (tid < KKK) {
        idx_out[b * KKK + tid]  = si[tid];
        idxf_out[b * KKK + tid] = (float)si[tid];
    }
}

// --------------------- alloc softmax + gather + renorm ----------------------
__global__ __launch_bounds__(256) void sel_kernel(
    const float* __restrict__ logits, const int* __restrict__ tk,
    float* __restrict__ sel_out)
{
    __shared__ float sl[1024];
    __shared__ float red[8];
    __shared__ float ssum;
    int b = blockIdx.x, tid = threadIdx.x;
    int wid = tid >> 5, lane = tid & 31;

    for (int c = tid; c < 1024; c += 256) sl[c] = logits[b * 1024 + c];
    __syncthreads();

    float mx = -1e30f;
    for (int c = tid; c < 1024; c += 256) mx = fmaxf(mx, sl[c]);
    #pragma unroll
    for (int o = 16; o > 0; o >>= 1) mx = fmaxf(mx, __shfl_xor_sync(~0u, mx, o));
    if (lane == 0) red[wid] = mx;
    __syncthreads();
    float bm = -1e30f;
    #pragma unroll
    for (int i = 0; i < 8; i++) bm = fmaxf(bm, red[i]);
    __syncthreads();

    float sum = 0.f;
    for (int c = tid; c < 1024; c += 256) {
        float e = expf(sl[c] - bm); sl[c] = e; sum += e;
    }
    #pragma unroll
    for (int o = 16; o > 0; o >>= 1) sum += __shfl_xor_sync(~0u, sum, o);
    if (lane == 0) red[wid] = sum;
    __syncthreads();
    float tot = 0.f;
    #pragma unroll
    for (int i = 0; i < 8; i++) tot += red[i];
    float inv = 1.f / tot;
    __syncthreads();
    for (int c = tid; c < 1024; c += 256) sl[c] *= inv;
    __syncthreads();

    if (tid == 0) {
        float s = 0.f;
        for (int kk = 0; kk < KKK; kk++) s += sl[tk[b * KKK + kk]];
        ssum = s;
    }
    __syncthreads();
    if (tid < KKK) {
        float v = sl[tk[b * KKK + tid]];
        sel_out[b * KKK + tid] = v / (ssum + 1e-12f);
    }
}

// ------------------------------- launcher -----------------------------------
static inline void launch_gemm(const float* A, const float* W, const float* bias,
                               float* C, int M, int N, int Kd, int relu)
{
    if ((M % 128 == 0) && (N % 128 == 0) && (Kd % 32 == 0)) {
        size_t smem = (size_t)G128_SMEM_FLOATS * sizeof(float);   // 66560 B
        cudaFuncSetAttribute(gemm128_kernel,
                             cudaFuncAttributeMaxDynamicSharedMemorySize, (int)smem);
        dim3 grid(N / 128, M / 128);
        gemm128_kernel<<<grid, 256, smem>>>(A, W, bias, C, M, N, Kd, relu);
    } else {
        dim3 grid(N / 64, M / 64);
        gemm_kernel<<<grid, 256>>>(A, W, bias, C, M, N, Kd, relu);
    }
}

extern "C" void kernel_launch(void* const* d_in, const int* in_sizes, int n_in,
                              void* d_out, int out_size)
{
    const float* x      = (const float*)d_in[0];
    const float* gumbel = (const float*)d_in[1];
    const float* emb_W  = (const float*)d_in[2];
    const float* emb_b  = (const float*)d_in[3];
    const float* Wq     = (const float*)d_in[4];
    const float* Wk     = (const float*)d_in[5];
    const float* Wv     = (const float*)d_in[6];
    const float* Wo     = (const float*)d_in[7];
    const float* ln1_g  = (const float*)d_in[8];
    const float* ln1_b  = (const float*)d_in[9];
    const float* ln2_g  = (const float*)d_in[10];
    const float* ln2_b  = (const float*)d_in[11];
    const float* ffn_W1 = (const float*)d_in[12];
    const float* ffn_b1 = (const float*)d_in[13];
    const float* ffn_W2 = (const float*)d_in[14];
    const float* ffn_b2 = (const float*)d_in[15];
    const float* sha_Wq = (const float*)d_in[16];
    const float* sha_Wk = (const float*)d_in[17];
    const float* aW1    = (const float*)d_in[18];
    const float* ab1    = (const float*)d_in[19];
    const float* aW2    = (const float*)d_in[20];
    const float* ab2    = (const float*)d_in[21];

    float* out     = (float*)d_out;
    float* out_w   = out;                  // [64*1024]
    float* out_idx = out + BB * NNQ;       // [64*64] indices as float
    float* out_sel = out_idx + BB * KKK;   // [64*64]

    float *ph, *pq, *pk, *pv, *po, *pffn, *phm, *pqv, *pt1, *plog;
    int* ptk;
    cudaGetSymbolAddress((void**)&ph,   g_h);
    cudaGetSymbolAddress((void**)&pq,   g_q);
    cudaGetSymbolAddress((void**)&pk,   g_k);
    cudaGetSymbolAddress((void**)&pv,   g_v);
    cudaGetSymbolAddress((void**)&po,   g_o);
    cudaGetSymbolAddress((void**)&pffn, g_ffn);
    cudaGetSymbolAddress((void**)&phm,  g_hmean);
    cudaGetSymbolAddress((void**)&pqv,  g_qv);
    cudaGetSymbolAddress((void**)&pt1,  g_t1);
    cudaGetSymbolAddress((void**)&plog, g_logits);
    cudaGetSymbolAddress((void**)&ptk,  g_topk);

    size_t attn_smem = (size_t)FATTN_SMEM_FLOATS * sizeof(float);   // 69632 B
    cudaFuncSetAttribute(fattn_kernel, cudaFuncAttributeMaxDynamicSharedMemorySize,
                         (int)attn_smem);

    // embed: h = x @ emb_W + emb_b  (K=16 -> small-GEMM path)
    launch_gemm(x, emb_W, emb_b, ph, TOK, DD, DIN, 0);

    for (int i = 0; i < LLL; i++) {
        const float* wq = Wq + (size_t)i * DD * DD;
        const float* wk = Wk + (size_t)i * DD * DD;
        const float* wv = Wv + (size_t)i * DD * DD;
        const float* wo = Wo + (size_t)i * DD * DD;

        launch_gemm(ph, wq, nullptr, pq, TOK, DD, DD, 0);
        launch_gemm(ph, wk, nullptr, pk, TOK, DD, DD, 0);
        launch_gemm(ph, wv, nullptr, pv, TOK, DD, DD, 0);

        fattn_kernel<<<dim3(NNQ / 64, BB * HH), 256, attn_smem>>>(pq, pk, pv, po);

        launch_gemm(po, wo, nullptr, pq, TOK, DD, DD, 0);
        lnres_kernel<<<TOK / 8, 256>>>(ph, pq, ln1_g + i * DD, ln1_b + i * DD);

        launch_gemm(ph, ffn_W1 + (size_t)i * DD * DFFN, ffn_b1 + i * DFFN,
                    pffn, TOK, DFFN, DD, 1);
        launch_gemm(pffn, ffn_W2 + (size_t)i * DFFN * DD, ffn_b2 + i * DD,
                    pq, TOK, DD, DFFN, 0);
        lnres_kernel<<<TOK / 8, 256>>>(ph, pq, ln2_g + i * DD, ln2_b + i * DD);
    }

    // head
    mean_kernel<<<BB, DD>>>(ph, phm);
    launch_gemm(phm, sha_Wq, nullptr, pqv, BB, DD, DD, 0);   // qv  [64,256]
    launch_gemm(ph, sha_Wk, nullptr, pk, TOK, DD, DD, 0);    // kv  [65536,256]

    score_kernel<<<BB, 256>>>(pqv, pk, gumbel, out_w);
    topk_kernel<<<BB, 512>>>(out_w, ptk, out_idx);

    launch_gemm(phm, aW1, ab1, pt1, BB, DD, DD, 1);          // relu(hmean@W1+b1)
    launch_gemm(pt1, aW2, ab2, plog, BB, NNQ, DD, 0);        // logits [64,1024]
    sel_kernel<<<BB, 256>>>(plog, ptk, out_sel);
}

// round 16
// speedup vs baseline: 2.0635x; 1.0098x over previous
#include <cuda_runtime.h>
#include <cstdint>

// ---------------------------------------------------------------------------
// ContActor: B=64, N=1024, D_IN=16, D=256, H=4, DH=64, L=3, DFF=1024, K=64
// Full fp32. Outputs (concatenated float32):
//   weights [64*1024], topk_idx (as float) [64*64], sel [64*64]
// Round 16: byte-identical resubmit (6th broker failure on this change-set).
// fattn: __expf + STS.128 P staging. gemm128: cp.async, BK=32.
// Baseline to beat: 12842us (round 9).
// ---------------------------------------------------------------------------

#define BB   64
#define NNQ  1024
#define DIN  16
#define DD   256
#define HH   4
#define DHH  64
#define LLL  3
#define DFFN 1024
#define KKK  64
#define TOK  (BB * NNQ)   // 65536

// ------------------------- scratch (device globals) ------------------------
__device__ float g_h  [(size_t)TOK * DD];
__device__ float g_q  [(size_t)TOK * DD];
__device__ float g_k  [(size_t)TOK * DD];
__device__ float g_v  [(size_t)TOK * DD];
__device__ float g_o  [(size_t)TOK * DD];
__device__ float g_ffn[(size_t)TOK * DFFN];
__device__ float g_hmean[BB * DD];
__device__ float g_qv   [BB * DD];
__device__ float g_t1   [BB * DD];
__device__ float g_logits[BB * NNQ];
__device__ int   g_topk  [BB * KKK];

// --------------------- big GEMM: 128x128 tile, BK=32, 8x8 micro -------------
#define BM 128
#define BN 128
#define BK 32
#define APS 132                         // As row pitch (floats)
#define G128_SMEM_FLOATS (2 * BK * APS + 2 * BK * BN)   // 8448 + 8192

__global__ __launch_bounds__(256, 2) void gemm128_kernel(
    const float* __restrict__ A, const float* __restrict__ W,
    const float* __restrict__ bias, float* __restrict__ C,
    int M, int N, int Kd, int do_relu)
{
    extern __shared__ float gsm[];
    float* As = gsm;                     // [2][BK][APS]  (k-major, m inner)
    float* Bs = gsm + 2 * BK * APS;      // [2][BK][BN]

    int tid = threadIdx.x;
    int m0 = blockIdx.y * BM, n0 = blockIdx.x * BN;

    int ar = tid >> 1;                  // 0..127 (A row)
    int ac = (tid & 1) << 4;            // 0 or 16 (A k-offset)
    int brow = tid >> 5;                // 0..7   (B row base)
    int bcol = (tid & 31) << 2;         // 0..124 (B col, 16B chunks)
    int tx = tid & 15, ty = tid >> 4;

    const int nt = Kd / BK;

    float acc[8][8] = {};
    float4 pa[4];

    uint32_t bs_base;
    asm("{ .reg .u64 t; cvta.to.shared.u64 t, %1; cvt.u32.u64 %0, t; }"
        : "=r"(bs_base) : "l"(Bs));

    // ---- prologue: stage 0 ----
    {
        const float* ap = A + (size_t)(m0 + ar) * Kd + ac;
        #pragma unroll
        for (int i = 0; i < 4; i++) pa[i] = *(const float4*)(ap + 4 * i);
        #pragma unroll
        for (int p = 0; p < 4; p++) {
            int r = brow + p * 8;
            uint32_t dst = bs_base + (uint32_t)((r * BN + bcol) * 4);
            const float* src = W + (size_t)r * N + n0 + bcol;
            asm volatile("cp.async.cg.shared.global [%0], [%1], 16;\n"
                         :: "r"(dst), "l"(src));
        }
        asm volatile("cp.async.commit_group;\n" ::: "memory");
        #pragma unroll
        for (int i = 0; i < 4; i++) {
            As[(ac + 4 * i + 0) * APS + ar] = pa[i].x;
            As[(ac + 4 * i + 1) * APS + ar] = pa[i].y;
            As[(ac + 4 * i + 2) * APS + ar] = pa[i].z;
            As[(ac + 4 * i + 3) * APS + ar] = pa[i].w;
        }
        asm volatile("cp.async.wait_group 0;\n" ::: "memory");
        __syncthreads();
    }

    for (int kt = 0; kt < nt; kt++) {
        int cur = kt & 1, nxt = cur ^ 1;

        // issue next stage (B async, A into regs) — overlaps compute below
        if (kt + 1 < nt) {
            int k0 = (kt + 1) * BK;
            const float* ap = A + (size_t)(m0 + ar) * Kd + k0 + ac;
            #pragma unroll
            for (int i = 0; i < 4; i++) pa[i] = *(const float4*)(ap + 4 * i);
            #pragma unroll
            for (int p = 0; p < 4; p++) {
                int r = brow + p * 8;
                uint32_t dst = bs_base + (uint32_t)(((nxt * BK + r) * BN + bcol) * 4);
                const float* src = W + (size_t)(k0 + r) * N + n0 + bcol;
                asm volatile("cp.async.cg.shared.global [%0], [%1], 16;\n"
                             :: "r"(dst), "l"(src));
            }
            asm volatile("cp.async.commit_group;\n" ::: "memory");
        }

        // compute current stage
        const float* Asc = As + cur * BK * APS;
        const float* Bsc = Bs + cur * BK * BN;
        #pragma unroll
        for (int k = 0; k < BK; k++) {
            float a[8], b[8];
            *(float4*)&a[0] = *(const float4*)&Asc[k * APS + ty * 8];
            *(float4*)&a[4] = *(const float4*)&Asc[k * APS + ty * 8 + 4];
            *(float4*)&b[0] = *(const float4*)&Bsc[k * BN + tx * 8];
            *(float4*)&b[4] = *(const float4*)&Bsc[k * BN + tx * 8 + 4];
            #pragma unroll
            for (int i = 0; i < 8; i++)
                #pragma unroll
                for (int j = 0; j < 8; j++)
                    acc[i][j] += a[i] * b[j];
        }

        // drain stage kt+1 into smem, wait for B, barrier
        if (kt + 1 < nt) {
            float* Asn = As + nxt * BK * APS;
            #pragma unroll
            for (int i = 0; i < 4; i++) {
                Asn[(ac + 4 * i + 0) * APS + ar] = pa[i].x;
                Asn[(ac + 4 * i + 1) * APS + ar] = pa[i].y;
                Asn[(ac + 4 * i + 2) * APS + ar] = pa[i].z;
                Asn[(ac + 4 * i + 3) * APS + ar] = pa[i].w;
            }
            asm volatile("cp.async.wait_group 0;\n" ::: "memory");
        }
        __syncthreads();
    }

    // epilogue
    #pragma unroll
    for (int i = 0; i < 8; i++) {
        float* crow = C + (size_t)(m0 + ty * 8 + i) * N + n0 + tx * 8;
        #pragma unroll
        for (int j4 = 0; j4 < 8; j4 += 4) {
            float4 o;
            float* po = (float*)&o;
            #pragma unroll
            for (int j = 0; j < 4; j++) {
                float v = acc[i][j4 + j];
                if (bias) v += bias[n0 + tx * 8 + j4 + j];
                if (do_relu) v = fmaxf(v, 0.f);
                po[j] = v;
            }
            *(float4*)(crow + j4) = o;
        }
    }
}

// --------------------- small GEMM: 64x64 tile, BK=32, 4x4 micro --------------
__global__ __launch_bounds__(256) void gemm_kernel(
    const float* __restrict__ A, const float* __restrict__ W,
    const float* __restrict__ bias, float* __restrict__ C,
    int M, int N, int Kd, int do_relu)
{
    __shared__ float As[64][36];
    __shared__ float Bs[32][64];
    int tid = threadIdx.x;
    int tx = tid & 15, ty = tid >> 4;
    int m0 = blockIdx.y << 6, n0 = blockIdx.x << 6;

    float acc[4][4] = {};

    for (int k0 = 0; k0 < Kd; k0 += 32) {
        {
            int r  = tid >> 3;
            int c4 = (tid & 7) << 2;
            #pragma unroll
            for (int rr = 0; rr < 64; rr += 32) {
                float4 val;
                if (k0 + c4 < Kd)
                    val = *(const float4*)(A + (size_t)(m0 + r + rr) * Kd + k0 + c4);
                else
                    val = make_float4(0.f, 0.f, 0.f, 0.f);
                *(float4*)&As[r + rr][c4] = val;
            }
        }
        {
            int r  = tid >> 4;
            int c4 = (tid & 15) << 2;
            #pragma unroll
            for (int rr = 0; rr < 32; rr += 16) {
                float4 val;
                if (k0 + r + rr < Kd)
                    val = *(const float4*)(W + (size_t)(k0 + r + rr) * N + n0 + c4);
                else
                    val = make_float4(0.f, 0.f, 0.f, 0.f);
                *(float4*)&Bs[r + rr][c4] = val;
            }
        }
        __syncthreads();
        #pragma unroll
        for (int k = 0; k < 32; k++) {
            float4 bv = *(float4*)&Bs[k][tx << 2];
            float b[4] = {bv.x, bv.y, bv.z, bv.w};
            float a[4];
            #pragma unroll
            for (int i = 0; i < 4; i++) a[i] = As[(ty << 2) + i][k];
            #pragma unroll
            for (int i = 0; i < 4; i++)
                #pragma unroll
                for (int j = 0; j < 4; j++)
                    acc[i][j] += a[i] * b[j];
        }
        __syncthreads();
    }

    #pragma unroll
    for (int i = 0; i < 4; i++) {
        float4 out;
        float* po = (float*)&out;
        #pragma unroll
        for (int j = 0; j < 4; j++) {
            float v = acc[i][j];
            if (bias) v += bias[n0 + (tx << 2) + j];
            if (do_relu) v = fmaxf(v, 0.f);
            po[j] = v;
        }
        *(float4*)(C + (size_t)(m0 + (ty << 2) + i) * N + n0 + (tx << 2)) = out;
    }
}

// ---------------------- flash attention (64q x 64k tiles) -------------------
#define APITCH 68   // floats per row (64 + 4 pad), 272B (16B aligned)
#define FATTN_SMEM_FLOATS (4 * 64 * APITCH)

__global__ __launch_bounds__(256, 2) void fattn_kernel(
    const float* __restrict__ Q, const float* __restrict__ Kf,
    const float* __restrict__ V, float* __restrict__ O)
{
    extern __shared__ float sm[];
    float* sQ = sm;                      // [d][q] swizzled
    float* sK = sQ + 64 * APITCH;        // [d][k] swizzled
    float* sV = sK + 64 * APITCH;        // [j][d] natural
    float* sS = sV + 64 * APITCH;        // [j][q] swizzled

    int tid = threadIdx.x;
    int tx = tid & 15, ty = tid >> 4;
    int bh = blockIdx.y;
    int b  = bh >> 2, h = bh & 3;
    int q0 = blockIdx.x << 6;
    size_t base = ((size_t)b * NNQ) * DD + h * DHH;

    // ---- load Q tile transposed ----
    #pragma unroll
    for (int it = 0; it < 4; it++) {
        int idx = tid + it * 256;
        int r = idx >> 4;            // 0..63
        int d4 = (idx & 15) << 2;    // 0..60
        float4 qv = *(const float4*)(Q + base + (size_t)(q0 + r) * DD + d4);
        int sw = ((d4 >> 2) & 7) << 2;
        int cbase = (((r >> 2) << 2) ^ sw) + (r & 3);
        sQ[(d4 + 0) * APITCH + cbase] = qv.x;
        sQ[(d4 + 1) * APITCH + cbase] = qv.y;
        sQ[(d4 + 2) * APITCH + cbase] = qv.z;
        sQ[(d4 + 3) * APITCH + cbase] = qv.w;
    }

    float m_i[4], l_i[4], o[4][4];
    #pragma unroll
    for (int i = 0; i < 4; i++) {
        m_i[i] = -1e30f; l_i[i] = 0.f;
        #pragma unroll
        for (int j = 0; j < 4; j++) o[i][j] = 0.f;
    }

    for (int kt = 0; kt < 16; kt++) {
        __syncthreads();

        // ---- load K tile transposed(+swizzle) and V tile natural ----
        #pragma unroll
        for (int it = 0; it < 4; it++) {
            int idx = tid + it * 256;
            int r = idx >> 4;
            int d4 = (idx & 15) << 2;
            size_t goff = base + (size_t)(kt * 64 + r) * DD + d4;
            float4 kv = *(const float4*)(Kf + goff);
            float4 vv = *(const float4*)(V + goff);
            int sw = ((d4 >> 2) & 7) << 2;
            int cbase = (((r >> 2) << 2) ^ sw) + (r & 3);
            sK[(d4 + 0) * APITCH + cbase] = kv.x;
            sK[(d4 + 1) * APITCH + cbase] = kv.y;
            sK[(d4 + 2) * APITCH + cbase] = kv.z;
            sK[(d4 + 3) * APITCH + cbase] = kv.w;
            *(float4*)&sV[r * APITCH + d4] = vv;
        }
        __syncthreads();

        // ---- S tile
        float s[4][4] = {};
        #pragma unroll 16
        for (int d = 0; d < 64; d++) {
            int sw = ((d >> 2) & 7) << 2;
            float4 a  = *(float4*)&sQ[d * APITCH + ((ty << 2) ^ sw)];
            float4 bq = *(float4*)&sK[d * APITCH + ((tx << 2) ^ sw)];
            float av[4] = {a.x, a.y, a.z, a.w};
            float bv[4] = {bq.x, bq.y, bq.z, bq.w};
            #pragma unroll
            for (int i = 0; i < 4; i++)
                #pragma unroll
                for (int j = 0; j < 4; j++)
                    s[i][j] += av[i] * bv[j];
        }

        // ---- online softmax update (fast exp: MUFU-based __expf)
        #pragma unroll
        for (int i = 0; i < 4; i++) {
            #pragma unroll
            for (int j = 0; j < 4; j++) s[i][j] *= 0.125f;
            float tm = fmaxf(fmaxf(s[i][0], s[i][1]), fmaxf(s[i][2], s[i][3]));
            #pragma unroll
            for (int off = 8; off > 0; off >>= 1)
                tm = fmaxf(tm, __shfl_xor_sync(0xffffffffu, tm, off));
            float mn = fmaxf(m_i[i], tm);
            float f = __expf(m_i[i] - mn);
            m_i[i] = mn;
            l_i[i] *= f;
            #pragma unroll
            for (int j = 0; j < 4; j++) o[i][j] *= f;
            float rs = 0.f;
            #pragma unroll
            for (int j = 0; j < 4; j++) {
                float p = __expf(s[i][j] - mn);
                s[i][j] = p; rs += p;
            }
            #pragma unroll
            for (int off = 8; off > 0; off >>= 1)
                rs += __shfl_xor_sync(0xffffffffu, rs, off);
            l_i[i] += rs;
        }

        // ---- stage P transposed (+swizzle), vectorized STS.128
        {
            int sw = (tx & 7) << 2;
            int cb = ((ty << 2) ^ sw);
            #pragma unroll
            for (int jj = 0; jj < 4; jj++) {
                float4 pv = make_float4(s[0][jj], s[1][jj], s[2][jj], s[3][jj]);
                *(float4*)&sS[(tx * 4 + jj) * APITCH + cb] = pv;
            }
        }
        __syncthreads();

        // ---- O += P V
        #pragma unroll 16
        for (int j = 0; j < 64; j++) {
            int sw = ((j >> 2) & 7) << 2;
            float4 a  = *(float4*)&sS[j * APITCH + ((ty << 2) ^ sw)];
            float4 bv = *(float4*)&sV[j * APITCH + (tx << 2)];
            float av[4] = {a.x, a.y, a.z, a.w};
            float vv[4] = {bv.x, bv.y, bv.z, bv.w};
            #pragma unroll
            for (int i = 0; i < 4; i++)
                #pragma unroll
                for (int k = 0; k < 4; k++)
                    o[i][k] += av[i] * vv[k];
        }
    }

    // ---- epilogue
    #pragma unroll
    for (int i = 0; i < 4; i++) {
        float inv = 1.f / l_i[i];
        float4 ov = make_float4(o[i][0] * inv, o[i][1] * inv,
                                o[i][2] * inv, o[i][3] * inv);
        *(float4*)(O + base + (size_t)(q0 + ty * 4 + i) * DD + (tx << 2)) = ov;
    }
}

// ------------------------- residual + layernorm -----------------------------
__global__ __launch_bounds__(256) void lnres_kernel(
    float* __restrict__ Hb, const float* __restrict__ R,
    const float* __restrict__ gam, const float* __restrict__ bet)
{
    int token = (blockIdx.x << 3) + (threadIdx.x >> 5);
    int lane  = threadIdx.x & 31;
    float* hr = Hb + (size_t)token * DD;
    const float* rr = R + (size_t)token * DD;

    float vals[8];
    float s = 0.f;
    #pragma unroll
    for (int t = 0; t < 8; t++) {
        float v = hr[lane + (t << 5)] + rr[lane + (t << 5)];
        vals[t] = v; s += v;
    }
    #pragma unroll
    for (int o = 16; o > 0; o >>= 1) s += __shfl_xor_sync(~0u, s, o);
    float mean = s * (1.f / 256.f);
    float vs = 0.f;
    #pragma unroll
    for (int t = 0; t < 8; t++) { float d = vals[t] - mean; vs += d * d; }
    #pragma unroll
    for (int o = 16; o > 0; o >>= 1) vs += __shfl_xor_sync(~0u, vs, o);
    float inv = 1.f / sqrtf(vs * (1.f / 256.f) + 1e-5f);
    #pragma unroll
    for (int t = 0; t < 8; t++) {
        int d = lane + (t << 5);
        hr[d] = (vals[t] - mean) * inv * gam[d] + bet[d];
    }
}

// ------------------------------- mean over N --------------------------------
__global__ void mean_kernel(const float* __restrict__ H, float* __restrict__ Hm)
{
    int b = blockIdx.x, d = threadIdx.x;
    const float* p = H + (size_t)b * NNQ * DD + d;
    float s = 0.f;
    for (int n = 0; n < NNQ; n++) s += p[(size_t)n * DD];
    Hm[b * DD + d] = s * (1.f / 1024.f);
}

// ---------------- scores + gumbel-softmax weights (per batch b) -------------
__global__ __launch_bounds__(256) void score_kernel(
    const float* __restrict__ QV, const float* __restrict__ KV,
    const float* __restrict__ gum, float* __restrict__ outw)
{
    __shared__ float sqv[256];
    __shared__ float ss[1024];
    __shared__ float red[8];
    int b = blockIdx.x, tid = threadIdx.x;
    int wid = tid >> 5, lane = tid & 31;

    sqv[tid] = QV[b * 256 + tid];
    __syncthreads();

    for (int n = wid; n < 1024; n += 8) {
        const float* kr = KV + ((size_t)b * NNQ + n) * DD;
        float s = 0.f;
        #pragma unroll
        for (int t = 0; t < 8; t++) s += sqv[lane + (t << 5)] * kr[lane + (t << 5)];
        #pragma unroll
        for (int o = 16; o > 0; o >>= 1) s += __shfl_xor_sync(~0u, s, o);
        if (lane == 0) ss[n] = (s * 0.0625f + gum[b * NNQ + n]) * 2.0f;
    }
    __syncthreads();

    float mx = -1e30f;
    for (int c = tid; c < 1024; c += 256) mx = fmaxf(mx, ss[c]);
    #pragma unroll
    for (int o = 16; o > 0; o >>= 1) mx = fmaxf(mx, __shfl_xor_sync(~0u, mx, o));
    if (lane == 0) red[wid] = mx;
    __syncthreads();
    float bm = -1e30f;
    #pragma unroll
    for (int i = 0; i < 8; i++) bm = fmaxf(bm, red[i]);
    __syncthreads();

    float sum = 0.f;
    for (int c = tid; c < 1024; c += 256) {
        float e = expf(ss[c] - bm); ss[c] = e; sum += e;
    }
    #pragma unroll
    for (int o = 16; o > 0; o >>= 1) sum += __shfl_xor_sync(~0u, sum, o);
    if (lane == 0) red[wid] = sum;
    __syncthreads();
    float tot = 0.f;
    #pragma unroll
    for (int i = 0; i < 8; i++) tot += red[i];
    float inv = 1.f / tot;
    for (int c = tid; c < 1024; c += 256)
        outw[b * NNQ + c] = ss[c] * inv;
}

// ------------------------- top-k via bitonic sort ---------------------------
__global__ __launch_bounds__(512) void topk_kernel(
    const float* __restrict__ Wts, int* __restrict__ idx_out,
    float* __restrict__ idxf_out)
{
    __shared__ float sv[1024];
    __shared__ int   si[1024];
    int b = blockIdx.x, tid = threadIdx.x;
    for (int i = tid; i < 1024; i += 512) { sv[i] = Wts[b * 1024 + i]; si[i] = i; }
    __syncthreads();
    for (int k = 2; k <= 1024; k <<= 1) {
        for (int j = k >> 1; j > 0; j >>= 1) {
            for (int i = tid; i < 1024; i += 512) {
                int ix = i ^ j;
                if (ix > i) {
                    bool up = ((i & k) == 0);
                    float v1 = sv[i], v2 = sv[ix];
                    int   i1 = si[i], i2 = si[ix];
                    bool before = (v1 > v2) || (v1 == v2 && i1 < i2);
                    if (up ? !before : before) {
                        sv[i] = v2; sv[ix] = v1;
                        si[i] = i2; si[ix] = i1;
                    }
                }
            }
            __syncthreads();
        }
    }
    if (tid < KKK) {
        idx_out[b * KKK + tid]  = si[tid];
        idxf_out[b * KKK + tid] = (float)si[tid];
    }
}

// --------------------- alloc softmax + gather + renorm ----------------------
__global__ __launch_bounds__(256) void sel_kernel(
    const float* __restrict__ logits, const int* __restrict__ tk,
    float* __restrict__ sel_out)
{
    __shared__ float sl[1024];
    __shared__ float red[8];
    __shared__ float ssum;
    int b = blockIdx.x, tid = threadIdx.x;
    int wid = tid >> 5, lane = tid & 31;

    for (int c = tid; c < 1024; c += 256) sl[c] = logits[b * 1024 + c];
    __syncthreads();

    float mx = -1e30f;
    for (int c = tid; c < 1024; c += 256) mx = fmaxf(mx, sl[c]);
    #pragma unroll
    for (int o = 16; o > 0; o >>= 1) mx = fmaxf(mx, __shfl_xor_sync(~0u, mx, o));
    if (lane == 0) red[wid] = mx;
    __syncthreads();
    float bm = -1e30f;
    #pragma unroll
    for (int i = 0; i < 8; i++) bm = fmaxf(bm, red[i]);
    __syncthreads();

    float sum = 0.f;
    for (int c = tid; c < 1024; c += 256) {
        float e = expf(sl[c] - bm); sl[c] = e; sum += e;
    }
    #pragma unroll
    for (int o = 16; o > 0; o >>= 1) sum += __shfl_xor_sync(~0u, sum, o);
    if (lane == 0) red[wid] = sum;
    __syncthreads();
    float tot = 0.f;
    #pragma unroll
    for (int i = 0; i < 8; i++) tot += red[i];
    float inv = 1.f / tot;
    __syncthreads();
    for (int c = tid; c < 1024; c += 256) sl[c] *= inv;
    __syncthreads();

    if (tid == 0) {
        float s = 0.f;
        for (int kk = 0; kk < KKK; kk++) s += sl[tk[b * KKK + kk]];
        ssum = s;
    }
    __syncthreads();
    if (tid < KKK) {
        float v = sl[tk[b * KKK + tid]];
        sel_out[b * KKK + tid] = v / (ssum + 1e-12f);
    }
}

// ------------------------------- launcher -----------------------------------
static inline void launch_gemm(const float* A, const float* W, const float* bias,
                               float* C, int M, int N, int Kd, int relu)
{
    if ((M % 128 == 0) && (N % 128 == 0) && (Kd % 32 == 0)) {
        size_t smem = (size_t)G128_SMEM_FLOATS * sizeof(float);   // 66560 B
        cudaFuncSetAttribute(gemm128_kernel,
                             cudaFuncAttributeMaxDynamicSharedMemorySize, (int)smem);
        dim3 grid(N / 128, M / 128);
        gemm128_kernel<<<grid, 256, smem>>>(A, W, bias, C, M, N, Kd, relu);
    } else {
        dim3 grid(N / 64, M / 64);
        gemm_kernel<<<grid, 256>>>(A, W, bias, C, M, N, Kd, relu);
    }
}

extern "C" void kernel_launch(void* const* d_in, const int* in_sizes, int n_in,
                              void* d_out, int out_size)
{
    const float* x      = (const float*)d_in[0];
    const float* gumbel = (const float*)d_in[1];
    const float* emb_W  = (const float*)d_in[2];
    const float* emb_b  = (const float*)d_in[3];
    const float* Wq     = (const float*)d_in[4];
    const float* Wk     = (const float*)d_in[5];
    const float* Wv     = (const float*)d_in[6];
    const float* Wo     = (const float*)d_in[7];
    const float* ln1_g  = (const float*)d_in[8];
    const float* ln1_b  = (const float*)d_in[9];
    const float* ln2_g  = (const float*)d_in[10];
    const float* ln2_b  = (const float*)d_in[11];
    const float* ffn_W1 = (const float*)d_in[12];
    const float* ffn_b1 = (const float*)d_in[13];
    const float* ffn_W2 = (const float*)d_in[14];
    const float* ffn_b2 = (const float*)d_in[15];
    const float* sha_Wq = (const float*)d_in[16];
    const float* sha_Wk = (const float*)d_in[17];
    const float* aW1    = (const float*)d_in[18];
    const float* ab1    = (const float*)d_in[19];
    const float* aW2    = (const float*)d_in[20];
    const float* ab2    = (const float*)d_in[21];

    float* out     = (float*)d_out;
    float* out_w   = out;                  // [64*1024]
    float* out_idx = out + BB * NNQ;       // [64*64] indices as float
    float* out_sel = out_idx + BB * KKK;   // [64*64]

    float *ph, *pq, *pk, *pv, *po, *pffn, *phm, *pqv, *pt1, *plog;
    int* ptk;
    cudaGetSymbolAddress((void**)&ph,   g_h);
    cudaGetSymbolAddress((void**)&pq,   g_q);
    cudaGetSymbolAddress((void**)&pk,   g_k);
    cudaGetSymbolAddress((void**)&pv,   g_v);
    cudaGetSymbolAddress((void**)&po,   g_o);
    cudaGetSymbolAddress((void**)&pffn, g_ffn);
    cudaGetSymbolAddress((void**)&phm,  g_hmean);
    cudaGetSymbolAddress((void**)&pqv,  g_qv);
    cudaGetSymbolAddress((void**)&pt1,  g_t1);
    cudaGetSymbolAddress((void**)&plog, g_logits);
    cudaGetSymbolAddress((void**)&ptk,  g_topk);

    size_t attn_smem = (size_t)FATTN_SMEM_FLOATS * sizeof(float);   // 69632 B
    cudaFuncSetAttribute(fattn_kernel, cudaFuncAttributeMaxDynamicSharedMemorySize,
                         (int)attn_smem);

    // embed: h = x @ emb_W + emb_b  (K=16 -> small-GEMM path)
    launch_gemm(x, emb_W, emb_b, ph, TOK, DD, DIN, 0);

    for (int i = 0; i < LLL; i++) {
        const float* wq = Wq + (size_t)i * DD * DD;
        const float* wk = Wk + (size_t)i * DD * DD;
        const float* wv = Wv + (size_t)i * DD * DD;
        const float* wo = Wo + (size_t)i * DD * DD;

        launch_gemm(ph, wq, nullptr, pq, TOK, DD, DD, 0);
        launch_gemm(ph, wk, nullptr, pk, TOK, DD, DD, 0);
        launch_gemm(ph, wv, nullptr, pv, TOK, DD, DD, 0);

        fattn_kernel<<<dim3(NNQ / 64, BB * HH), 256, attn_smem>>>(pq, pk, pv, po);

        launch_gemm(po, wo, nullptr, pq, TOK, DD, DD, 0);
        lnres_kernel<<<TOK / 8, 256>>>(ph, pq, ln1_g + i * DD, ln1_b + i * DD);

        launch_gemm(ph, ffn_W1 + (size_t)i * DD * DFFN, ffn_b1 + i * DFFN,
                    pffn, TOK, DFFN, DD, 1);
        launch_gemm(pffn, ffn_W2 + (size_t)i * DFFN * DD, ffn_b2 + i * DD,
                    pq, TOK, DD, DFFN, 0);
        lnres_kernel<<<TOK / 8, 256>>>(ph, pq, ln2_g + i * DD, ln2_b + i * DD);
    }

    // head
    mean_kernel<<<BB, DD>>>(ph, phm);
    launch_gemm(phm, sha_Wq, nullptr, pqv, BB, DD, DD, 0);   // qv  [64,256]
    launch_gemm(ph, sha_Wk, nullptr, pk, TOK, DD, DD, 0);    // kv  [65536,256]

    score_kernel<<<BB, 256>>>(pqv, pk, gumbel, out_w);
    topk_kernel<<<BB, 512>>>(out_w, ptk, out_idx);

    launch_gemm(phm, aW1, ab1, pt1, BB, DD, DD, 1);          // relu(hmean@W1+b1)
    launch_gemm(pt1, aW2, ab2, plog, BB, NNQ, DD, 0);        // logits [64,1024]
    sel_kernel<<<BB, 256>>>(plog, ptk, out_sel);
}